// round 8
// baseline (speedup 1.0000x reference)
#include <cuda_runtime.h>
#include <cuda_bf16.h>
#include <math.h>

#define L_TOK 131072
#define C_DIM 192
#define QKV_DIM 576
#define FF_DIM 768
#define NWIN 2048

// scratch (device globals)
__device__ __nv_bfloat16 g_bufA[(size_t)L_TOK * C_DIM];   // LN out (bf16)
__device__ __nv_bfloat16 g_qkv [(size_t)L_TOK * QKV_DIM]; // QKV (bf16)
__device__ __nv_bfloat16 g_obuf[(size_t)L_TOK * C_DIM];   // attn out (bf16)
__device__ __nv_bfloat16 g_bufT[(size_t)L_TOK * FF_DIM];  // MLP hidden (bf16)
__device__ __nv_bfloat16 g_wbf [884736];                  // bf16 weights

__device__ __forceinline__ void cp_async16(void* smem, const void* gmem) {
    unsigned saddr = (unsigned)__cvta_generic_to_shared(smem);
    asm volatile("cp.async.cg.shared.global [%0], [%1], 16;\n" :: "r"(saddr), "l"(gmem));
}

__device__ __forceinline__ void ldsm_x4(unsigned& r0, unsigned& r1,
                                        unsigned& r2, unsigned& r3, unsigned addr) {
    asm volatile("ldmatrix.sync.aligned.m8n8.x4.shared.b16 {%0,%1,%2,%3}, [%4];"
                 : "=r"(r0), "=r"(r1), "=r"(r2), "=r"(r3) : "r"(addr));
}
__device__ __forceinline__ void ldsm_x4_t(unsigned& r0, unsigned& r1,
                                          unsigned& r2, unsigned& r3, unsigned addr) {
    asm volatile("ldmatrix.sync.aligned.m8n8.x4.trans.shared.b16 {%0,%1,%2,%3}, [%4];"
                 : "=r"(r0), "=r"(r1), "=r"(r2), "=r"(r3) : "r"(addr));
}

__device__ __forceinline__ void mma16816(float* c, unsigned a0, unsigned a1,
                                         unsigned a2, unsigned a3,
                                         unsigned b0, unsigned b1) {
    asm volatile(
        "mma.sync.aligned.m16n8k16.row.col.f32.bf16.bf16.f32 "
        "{%0,%1,%2,%3},{%4,%5,%6,%7},{%8,%9},{%0,%1,%2,%3};"
        : "+f"(c[0]), "+f"(c[1]), "+f"(c[2]), "+f"(c[3])
        : "r"(a0), "r"(a1), "r"(a2), "r"(a3), "r"(b0), "r"(b1));
}

// ---------------------------------------------------------------------------
// Fused weight conversion
// ---------------------------------------------------------------------------
struct WcvtArgs {
    const float* src[8];
    int off[9];
};

__global__ void cvt_weights_kernel(WcvtArgs a, __nv_bfloat16* __restrict__ out)
{
    int i = blockIdx.x * 256 + threadIdx.x;
    if (i >= a.off[8]) return;
    int s = 0;
#pragma unroll
    for (int j = 1; j < 8; j++) s += (i >= a.off[j]);
    out[i] = __float2bfloat16(a.src[s][i - a.off[s]]);
}

// ---------------------------------------------------------------------------
// LayerNorm (standalone; only for the very first LN on the fp32 input)
// ---------------------------------------------------------------------------
__global__ void ln_kernel(const float* __restrict__ x,
                          const float* __restrict__ g,
                          const float* __restrict__ b,
                          __nv_bfloat16* __restrict__ out)
{
    int row  = blockIdx.x * 8 + threadIdx.y;
    int lane = threadIdx.x;
    const float* xr = x + (size_t)row * C_DIM;
    float v[6];
    float s = 0.f;
#pragma unroll
    for (int i = 0; i < 6; i++) { v[i] = xr[lane + i * 32]; s += v[i]; }
#pragma unroll
    for (int o = 16; o; o >>= 1) s += __shfl_xor_sync(0xffffffffu, s, o);
    float mu = s * (1.0f / 192.0f);
    float vs = 0.f;
#pragma unroll
    for (int i = 0; i < 6; i++) { float d = v[i] - mu; vs += d * d; }
#pragma unroll
    for (int o = 16; o; o >>= 1) vs += __shfl_xor_sync(0xffffffffu, vs, o);
    float rstd = rsqrtf(vs * (1.0f / 192.0f) + 1e-5f);
    __nv_bfloat16* orow = out + (size_t)row * C_DIM;
#pragma unroll
    for (int i = 0; i < 6; i++) {
        int c = lane + i * 32;
        orow[c] = __float2bfloat16((v[i] - mu) * rstd * g[c] + b[c]);
    }
}

// ---------------------------------------------------------------------------
// bf16 GEMM: BM=64, BN=192, BK=32, 256 thr, 8 warps (2m x 4n), warp 32x48.
// 2-stage cp.async, static smem ~38 KB, 2 CTAs/SM.
// Optional fused LN over the (residual-added) output rows (BN==full row).
// ---------------------------------------------------------------------------
#define GBM 64
#define GBN 192
#define GBK 32
#define ASTRH 40
#define BSTRH 200
#define ASTAGE (GBM * ASTRH * 2)   // 5120 B
#define BSTAGE (GBK * BSTRH * 2)   // 12800 B

template<bool DOGELU, bool RES, bool OUTBF, bool DOLN>
__global__ __launch_bounds__(256, 2)
void gemm_bf16(const __nv_bfloat16* __restrict__ A,
               const __nv_bfloat16* __restrict__ B,
               const float* __restrict__ bias, const float* __restrict__ res,
               void* __restrict__ Cout,
               const float* __restrict__ lng, const float* __restrict__ lnb,
               __nv_bfloat16* __restrict__ lnout,
               int M, int N, int K)
{
    __shared__ __nv_bfloat16 As[2][GBM * ASTRH];
    __shared__ __nv_bfloat16 Bs[2][GBK * BSTRH];
    __shared__ float2 lnred[4][GBM];          // [n-warp][row] (sum, sumsq)

    int tid = threadIdx.x;
    int bm = blockIdx.y * GBM;
    int bn = blockIdx.x * GBN;
    int wid = tid >> 5, lane = tid & 31;
    int wm = (wid & 1) * 32, wn = (wid >> 1) * 48;
    int g = lane >> 2, t = lane & 3;

    int ldrow = (lane & 7) + ((lane >> 3) & 1) * 8;
    int ldcol = (lane >> 4) * 8;

    unsigned sA0 = (unsigned)__cvta_generic_to_shared(&As[0][0]);
    unsigned sB0 = (unsigned)__cvta_generic_to_shared(&Bs[0][0]);
    unsigned aBase = sA0 + (unsigned)(((wm + ldrow) * ASTRH + ldcol) * 2);
    unsigned bBase = sB0 + (unsigned)((ldrow * BSTRH + wn + ldcol) * 2);

    float acc[2][6][4];
#pragma unroll
    for (int a = 0; a < 2; a++)
#pragma unroll
        for (int j = 0; j < 6; j++)
#pragma unroll
            for (int c = 0; c < 4; c++) acc[a][j][c] = 0.f;

    auto loadA = [&](int stage, int k0) {
        int m = tid >> 2;               // 64 rows x 4 chunks = 256
        int c = (tid & 3) * 8;
        cp_async16(&As[stage][m * ASTRH + c],
                   A + (size_t)(bm + m) * K + k0 + c);
    };
    auto loadB = [&](int stage, int k0) {
#pragma unroll
        for (int l = 0; l < 3; l++) {
            int idx = tid + l * 256;    // 32 rows x 24 chunks = 768
            if (idx < 768) {
                int r = idx / 24;
                int c = (idx % 24) * 8;
                cp_async16(&Bs[stage][r * BSTRH + c],
                           B + (size_t)(k0 + r) * N + bn + c);
            }
        }
    };

    int nk = K / GBK;
    loadA(0, 0); loadB(0, 0);
    asm volatile("cp.async.commit_group;");

    for (int kb = 0; kb < nk; kb++) {
        if (kb + 1 < nk) {
            loadA((kb + 1) & 1, (kb + 1) * GBK);
            loadB((kb + 1) & 1, (kb + 1) * GBK);
            asm volatile("cp.async.commit_group;");
            asm volatile("cp.async.wait_group 1;");
        } else {
            asm volatile("cp.async.wait_group 0;");
        }
        __syncthreads();

        unsigned aS = aBase + (kb & 1) * ASTAGE;
        unsigned bS = bBase + (kb & 1) * BSTAGE;
#pragma unroll
        for (int ks = 0; ks < 2; ks++) {
            unsigned af[2][4], bfr[3][4];
#pragma unroll
            for (int mt = 0; mt < 2; mt++)
                ldsm_x4(af[mt][0], af[mt][1], af[mt][2], af[mt][3],
                        aS + mt * (16 * ASTRH * 2) + ks * 32);
#pragma unroll
            for (int nt = 0; nt < 3; nt++)
                ldsm_x4_t(bfr[nt][0], bfr[nt][1], bfr[nt][2], bfr[nt][3],
                          bS + ks * (16 * BSTRH * 2) + nt * 32);
#pragma unroll
            for (int mt = 0; mt < 2; mt++)
#pragma unroll
                for (int nt = 0; nt < 3; nt++) {
                    mma16816(acc[mt][nt * 2],     af[mt][0], af[mt][1],
                             af[mt][2], af[mt][3], bfr[nt][0], bfr[nt][1]);
                    mma16816(acc[mt][nt * 2 + 1], af[mt][0], af[mt][1],
                             af[mt][2], af[mt][3], bfr[nt][2], bfr[nt][3]);
                }
        }
        __syncthreads();
    }

    // ---- epilogue: bias (+GELU) (+res) -> write; optional fused LN ----
    float rsum[4] = {0.f, 0.f, 0.f, 0.f};
    float rsq [4] = {0.f, 0.f, 0.f, 0.f};

#pragma unroll
    for (int mt = 0; mt < 2; mt++)
#pragma unroll
        for (int j = 0; j < 6; j++) {
            int col = bn + wn + j * 8 + 2 * t;
            float2 bv = *(const float2*)(bias + col);
#pragma unroll
            for (int hf = 0; hf < 2; hf++) {
                int row = bm + wm + mt * 16 + g + hf * 8;
                float x0 = acc[mt][j][hf * 2 + 0] + bv.x;
                float x1 = acc[mt][j][hf * 2 + 1] + bv.y;
                if (DOGELU) {
                    x0 = 0.5f * x0 * (1.0f + erff(x0 * 0.70710678118654752f));
                    x1 = 0.5f * x1 * (1.0f + erff(x1 * 0.70710678118654752f));
                }
                if (RES) {
                    float2 r = *(const float2*)(res + (size_t)row * N + col);
                    x0 += r.x; x1 += r.y;
                }
                if (OUTBF) {
                    __nv_bfloat162* p = (__nv_bfloat162*)
                        ((__nv_bfloat16*)Cout + (size_t)row * N + col);
                    *p = __floats2bfloat162_rn(x0, x1);
                } else {
                    *(float2*)((float*)Cout + (size_t)row * N + col)
                        = make_float2(x0, x1);
                }
                if (DOLN) {
                    acc[mt][j][hf * 2 + 0] = x0;
                    acc[mt][j][hf * 2 + 1] = x1;
                    rsum[mt * 2 + hf] += x0 + x1;
                    rsq [mt * 2 + hf] += x0 * x0 + x1 * x1;
                }
            }
        }

    if (DOLN) {
        // quad-reduce (lanes g*4+t share a row set)
#pragma unroll
        for (int i = 0; i < 4; i++) {
            rsum[i] += __shfl_xor_sync(0xffffffffu, rsum[i], 1);
            rsum[i] += __shfl_xor_sync(0xffffffffu, rsum[i], 2);
            rsq [i] += __shfl_xor_sync(0xffffffffu, rsq [i], 1);
            rsq [i] += __shfl_xor_sync(0xffffffffu, rsq [i], 2);
        }
        int nw = wid >> 1;
        if (t == 0) {
#pragma unroll
            for (int mt = 0; mt < 2; mt++)
#pragma unroll
                for (int hf = 0; hf < 2; hf++) {
                    int lrow = wm + mt * 16 + g + hf * 8;
                    lnred[nw][lrow] = make_float2(rsum[mt * 2 + hf],
                                                  rsq [mt * 2 + hf]);
                }
        }
        __syncthreads();

        float mu[4], rstd[4];
#pragma unroll
        for (int mt = 0; mt < 2; mt++)
#pragma unroll
            for (int hf = 0; hf < 2; hf++) {
                int lrow = wm + mt * 16 + g + hf * 8;
                float s = 0.f, q = 0.f;
#pragma unroll
                for (int w = 0; w < 4; w++) {
                    float2 v = lnred[w][lrow];
                    s += v.x; q += v.y;
                }
                float m_ = s * (1.0f / 192.0f);
                float var = q * (1.0f / 192.0f) - m_ * m_;
                mu[mt * 2 + hf] = m_;
                rstd[mt * 2 + hf] = rsqrtf(var + 1e-5f);
            }

#pragma unroll
        for (int mt = 0; mt < 2; mt++)
#pragma unroll
            for (int j = 0; j < 6; j++) {
                int col = bn + wn + j * 8 + 2 * t;
                float2 gv = *(const float2*)(lng + col);
                float2 bv2 = *(const float2*)(lnb + col);
#pragma unroll
                for (int hf = 0; hf < 2; hf++) {
                    int row = bm + wm + mt * 16 + g + hf * 8;
                    float m_ = mu[mt * 2 + hf], rs = rstd[mt * 2 + hf];
                    float l0 = (acc[mt][j][hf * 2 + 0] - m_) * rs * gv.x + bv2.x;
                    float l1 = (acc[mt][j][hf * 2 + 1] - m_) * rs * gv.y + bv2.y;
                    *(__nv_bfloat162*)(lnout + (size_t)row * N + col)
                        = __floats2bfloat162_rn(l0, l1);
                }
            }
    }
}

// ---------------------------------------------------------------------------
// Tensor-core window attention (Round-7, unchanged)
// ---------------------------------------------------------------------------
__global__ __launch_bounds__(128)
void attn_tc_kernel(const __nv_bfloat16* __restrict__ qkv,
                    const float* __restrict__ rpb,
                    __nv_bfloat16* __restrict__ O, int shifted)
{
    __shared__ __nv_bfloat16 Qs[64 * 40];
    __shared__ __nv_bfloat16 Ks[64 * 40];
    __shared__ __nv_bfloat16 Vs[64 * 40];
    __shared__ float rpbs[2058];
    __shared__ int tok[64];
    __shared__ int regid[64];

    int tid = threadIdx.x;
    int wq = tid >> 5, lane = tid & 31;
    int g = lane >> 2, t = lane & 3;
    int win = blockIdx.x;
    int ws = win >> 8, wh = (win >> 4) & 15, ww = win & 15;

    if (tid < 64) {
        int i = tid >> 4, j = (tid >> 2) & 3, k = tid & 3;
        int cs = ws * 4 + i, ch = wh * 4 + j, cw = ww * 4 + k;
        int sg, hg, wg;
        if (shifted) { sg = (cs + 2) & 31; hg = (ch + 2) & 63; wg = (cw + 2) & 63; }
        else         { sg = cs;            hg = ch;            wg = cw; }
        tok[tid] = (sg * 64 + hg) * 64 + wg;
        int rs = cs < 28 ? 0 : (cs < 30 ? 1 : 2);
        int rh = ch < 60 ? 0 : (ch < 62 ? 1 : 2);
        int rw = cw < 60 ? 0 : (cw < 62 ? 1 : 2);
        regid[tid] = rs * 9 + rh * 3 + rw;
    }
    for (int i = tid; i < 2058; i += 128) rpbs[i] = rpb[i];
    __syncthreads();

    int r0 = wq * 16 + g;
    int r1 = r0 + 8;
    int i0 = r0 >> 4, j0 = (r0 >> 2) & 3, k0 = r0 & 3;
    int i1 = r1 >> 4, j1 = (r1 >> 2) & 3, k1 = r1 & 3;
    int reg0 = regid[r0], reg1 = regid[r1];
    size_t ob0 = (size_t)tok[r0] * C_DIM;
    size_t ob1 = (size_t)tok[r1] * C_DIM;

    int ldrow = (lane & 7) + ((lane >> 3) & 1) * 8;
    int ldcol = (lane >> 4) * 8;
    unsigned qB = (unsigned)__cvta_generic_to_shared(Qs)
                + (unsigned)(((wq * 16 + ldrow) * 40 + ldcol) * 2);
    unsigned kB = (unsigned)__cvta_generic_to_shared(Ks)
                + (unsigned)((ldrow * 40 + ldcol) * 2);
    unsigned vB = (unsigned)__cvta_generic_to_shared(Vs)
                + (unsigned)((ldrow * 40 + ldcol) * 2);

    const float scale = 0.17677669529663687f;

    for (int h = 0; h < 6; h++) {
#pragma unroll
        for (int l = 0; l < 2; l++) {
            int idx = tid + l * 128;
            int row = idx >> 2;
            int c = (idx & 3) * 8;
            const __nv_bfloat16* src = qkv + (size_t)tok[row] * QKV_DIM + h * 32 + c;
            cp_async16(&Qs[row * 40 + c], src);
            cp_async16(&Ks[row * 40 + c], src + 192);
            cp_async16(&Vs[row * 40 + c], src + 384);
        }
        asm volatile("cp.async.commit_group;");
        asm volatile("cp.async.wait_group 0;");
        __syncthreads();

        float s[8][4];
#pragma unroll
        for (int j = 0; j < 8; j++)
#pragma unroll
            for (int e = 0; e < 4; e++) s[j][e] = 0.f;

#pragma unroll
        for (int ks = 0; ks < 2; ks++) {
            unsigned a0, a1, a2, a3;
            ldsm_x4(a0, a1, a2, a3, qB + ks * 32);
#pragma unroll
            for (int nc = 0; nc < 4; nc++) {
                unsigned kr0, kr1, kr2, kr3;
                ldsm_x4(kr0, kr1, kr2, kr3, kB + nc * (16 * 80) + ks * 32);
                mma16816(s[nc * 2],     a0, a1, a2, a3, kr0, kr2);
                mma16816(s[nc * 2 + 1], a0, a1, a2, a3, kr1, kr3);
            }
        }

#pragma unroll
        for (int j = 0; j < 8; j++) {
            int cb = j * 8 + 2 * t;
#pragma unroll
            for (int e = 0; e < 4; e++) {
                int m = cb + (e & 1);
                int im = m >> 4, jm = (m >> 2) & 3, km = m & 3;
                float val;
                if (e < 2) {
                    int idx = (i0 - im + 3) * 49 + (j0 - jm + 3) * 7 + (k0 - km + 3);
                    val = s[j][e] * scale + rpbs[idx * 6 + h];
                    if (shifted && (reg0 != regid[m])) val -= 100.f;
                } else {
                    int idx = (i1 - im + 3) * 49 + (j1 - jm + 3) * 7 + (k1 - km + 3);
                    val = s[j][e] * scale + rpbs[idx * 6 + h];
                    if (shifted && (reg1 != regid[m])) val -= 100.f;
                }
                s[j][e] = val;
            }
        }

        float mx0 = -1e30f, mx1 = -1e30f;
#pragma unroll
        for (int j = 0; j < 8; j++) {
            mx0 = fmaxf(mx0, fmaxf(s[j][0], s[j][1]));
            mx1 = fmaxf(mx1, fmaxf(s[j][2], s[j][3]));
        }
        mx0 = fmaxf(mx0, __shfl_xor_sync(0xffffffffu, mx0, 1));
        mx0 = fmaxf(mx0, __shfl_xor_sync(0xffffffffu, mx0, 2));
        mx1 = fmaxf(mx1, __shfl_xor_sync(0xffffffffu, mx1, 1));
        mx1 = fmaxf(mx1, __shfl_xor_sync(0xffffffffu, mx1, 2));
        float sum0 = 0.f, sum1 = 0.f;
#pragma unroll
        for (int j = 0; j < 8; j++) {
            s[j][0] = __expf(s[j][0] - mx0);
            s[j][1] = __expf(s[j][1] - mx0);
            s[j][2] = __expf(s[j][2] - mx1);
            s[j][3] = __expf(s[j][3] - mx1);
            sum0 += s[j][0] + s[j][1];
            sum1 += s[j][2] + s[j][3];
        }
        sum0 += __shfl_xor_sync(0xffffffffu, sum0, 1);
        sum0 += __shfl_xor_sync(0xffffffffu, sum0, 2);
        sum1 += __shfl_xor_sync(0xffffffffu, sum1, 1);
        sum1 += __shfl_xor_sync(0xffffffffu, sum1, 2);
        float inv0 = 1.0f / sum0, inv1 = 1.0f / sum1;

        unsigned pa[4][4];
#pragma unroll
        for (int kk = 0; kk < 4; kk++) {
            __nv_bfloat162 p0 = __floats2bfloat162_rn(s[2 * kk][0],     s[2 * kk][1]);
            __nv_bfloat162 p1 = __floats2bfloat162_rn(s[2 * kk][2],     s[2 * kk][3]);
            __nv_bfloat162 p2 = __floats2bfloat162_rn(s[2 * kk + 1][0], s[2 * kk + 1][1]);
            __nv_bfloat162 p3 = __floats2bfloat162_rn(s[2 * kk + 1][2], s[2 * kk + 1][3]);
            pa[kk][0] = *(unsigned*)&p0;
            pa[kk][1] = *(unsigned*)&p1;
            pa[kk][2] = *(unsigned*)&p2;
            pa[kk][3] = *(unsigned*)&p3;
        }

        float o[4][4];
#pragma unroll
        for (int j = 0; j < 4; j++)
#pragma unroll
            for (int e = 0; e < 4; e++) o[j][e] = 0.f;

#pragma unroll
        for (int kk = 0; kk < 4; kk++) {
            unsigned v0, v1, v2, v3;
            ldsm_x4_t(v0, v1, v2, v3, vB + kk * (16 * 80));
            mma16816(o[0], pa[kk][0], pa[kk][1], pa[kk][2], pa[kk][3], v0, v1);
            mma16816(o[1], pa[kk][0], pa[kk][1], pa[kk][2], pa[kk][3], v2, v3);
            unsigned w0, w1, w2, w3;
            ldsm_x4_t(w0, w1, w2, w3, vB + kk * (16 * 80) + 32);
            mma16816(o[2], pa[kk][0], pa[kk][1], pa[kk][2], pa[kk][3], w0, w1);
            mma16816(o[3], pa[kk][0], pa[kk][1], pa[kk][2], pa[kk][3], w2, w3);
        }

#pragma unroll
        for (int nt = 0; nt < 4; nt++) {
            int col = h * 32 + nt * 8 + 2 * t;
            *(__nv_bfloat162*)(O + ob0 + col) =
                __floats2bfloat162_rn(o[nt][0] * inv0, o[nt][1] * inv0);
            *(__nv_bfloat162*)(O + ob1 + col) =
                __floats2bfloat162_rn(o[nt][2] * inv1, o[nt][3] * inv1);
        }
        __syncthreads();
    }
}

// ---------------------------------------------------------------------------
extern "C" void kernel_launch(void* const* d_in, const int* in_sizes, int n_in,
                              void* d_out, int out_size)
{
    (void)in_sizes; (void)n_in; (void)out_size;
    const float* x = (const float*)d_in[0];
    float* out = (float*)d_out;

    __nv_bfloat16 *bufA, *qkv, *obuf, *bufT, *wbf;
    cudaGetSymbolAddress((void**)&bufA, g_bufA);
    cudaGetSymbolAddress((void**)&qkv,  g_qkv);
    cudaGetSymbolAddress((void**)&obuf, g_obuf);
    cudaGetSymbolAddress((void**)&bufT, g_bufT);
    cudaGetSymbolAddress((void**)&wbf,  g_wbf);

    const int SZ_QW = C_DIM * QKV_DIM;
    const int SZ_PW = C_DIM * C_DIM;
    const int SZ_F1 = C_DIM * FF_DIM;
    const int SZ_F2 = FF_DIM * C_DIM;

    const int widx[8] = { 3, 6, 10, 12, 16, 19, 23, 25 };
    const int wsz [8] = { SZ_QW, SZ_PW, SZ_F1, SZ_F2, SZ_QW, SZ_PW, SZ_F1, SZ_F2 };

    WcvtArgs wa;
    int off = 0;
    __nv_bfloat16* wp[8];
    for (int i = 0; i < 8; i++) {
        wa.src[i] = (const float*)d_in[widx[i]];
        wa.off[i] = off;
        wp[i] = wbf + off;
        off += wsz[i];
    }
    wa.off[8] = off;
    cvt_weights_kernel<<<(off + 255) / 256, 256>>>(wa, wbf);

    const int MY = L_TOK / GBM;   // 2048
    dim3 lnBlk(32, 8);

    // ---------------- block 0 (unshifted) ----------------
    // LN1 on fp32 input
    ln_kernel<<<L_TOK / 8, lnBlk>>>(x, (const float*)d_in[1],
                                    (const float*)d_in[2], bufA);
    // qkv
    gemm_bf16<false, false, true, false><<<dim3(QKV_DIM / GBN, MY), 256>>>(
        bufA, wp[0], (const float*)d_in[4], nullptr, qkv,
        nullptr, nullptr, nullptr, L_TOK, QKV_DIM, C_DIM);
    attn_tc_kernel<<<NWIN, 128>>>(qkv, (const float*)d_in[5], obuf, 0);
    // proj + residual(x) -> out (fp32) ; fused LN2 -> bufA
    gemm_bf16<false, true, false, true><<<dim3(C_DIM / GBN, MY), 256>>>(
        obuf, wp[1], (const float*)d_in[7], x, out,
        (const float*)d_in[8], (const float*)d_in[9], bufA,
        L_TOK, C_DIM, C_DIM);
    // f1 + GELU
    gemm_bf16<true, false, true, false><<<dim3(FF_DIM / GBN, MY), 256>>>(
        bufA, wp[2], (const float*)d_in[11], nullptr, bufT,
        nullptr, nullptr, nullptr, L_TOK, FF_DIM, C_DIM);
    // f2 + residual(out) -> out ; fused LN1 of block 1 -> bufA
    gemm_bf16<false, true, false, true><<<dim3(C_DIM / GBN, MY), 256>>>(
        bufT, wp[3], (const float*)d_in[13], out, out,
        (const float*)d_in[14], (const float*)d_in[15], bufA,
        L_TOK, C_DIM, FF_DIM);

    // ---------------- block 1 (shifted) ----------------
    gemm_bf16<false, false, true, false><<<dim3(QKV_DIM / GBN, MY), 256>>>(
        bufA, wp[4], (const float*)d_in[17], nullptr, qkv,
        nullptr, nullptr, nullptr, L_TOK, QKV_DIM, C_DIM);
    attn_tc_kernel<<<NWIN, 128>>>(qkv, (const float*)d_in[18], obuf, 1);
    // proj + residual(out) -> out ; fused LN2 -> bufA
    gemm_bf16<false, true, false, true><<<dim3(C_DIM / GBN, MY), 256>>>(
        obuf, wp[5], (const float*)d_in[20], out, out,
        (const float*)d_in[21], (const float*)d_in[22], bufA,
        L_TOK, C_DIM, C_DIM);
    gemm_bf16<true, false, true, false><<<dim3(FF_DIM / GBN, MY), 256>>>(
        bufA, wp[6], (const float*)d_in[24], nullptr, bufT,
        nullptr, nullptr, nullptr, L_TOK, FF_DIM, C_DIM);
    // final f2 + residual -> out (no LN)
    gemm_bf16<false, true, false, false><<<dim3(C_DIM / GBN, MY), 256>>>(
        bufT, wp[7], (const float*)d_in[26], out, out,
        nullptr, nullptr, nullptr, L_TOK, C_DIM, FF_DIM);
}

// round 9
// speedup vs baseline: 1.1362x; 1.1362x over previous
#include <cuda_runtime.h>
#include <cuda_bf16.h>
#include <math.h>

#define L_TOK 131072
#define C_DIM 192
#define QKV_DIM 576
#define FF_DIM 768
#define NWIN 2048

// scratch (device globals)
__device__ __nv_bfloat16 g_bufA[(size_t)L_TOK * C_DIM];   // LN out (bf16)
__device__ __nv_bfloat16 g_qkv [(size_t)L_TOK * QKV_DIM]; // QKV (bf16)
__device__ __nv_bfloat16 g_obuf[(size_t)L_TOK * C_DIM];   // attn out (bf16)
__device__ __nv_bfloat16 g_bufT[(size_t)L_TOK * FF_DIM];  // MLP hidden (bf16)
__device__ __nv_bfloat16 g_wbf [884736];                  // bf16 weights

__device__ __forceinline__ void cp_async16(void* smem, const void* gmem) {
    unsigned saddr = (unsigned)__cvta_generic_to_shared(smem);
    asm volatile("cp.async.cg.shared.global [%0], [%1], 16;\n" :: "r"(saddr), "l"(gmem));
}

__device__ __forceinline__ void ldsm_x4(unsigned& r0, unsigned& r1,
                                        unsigned& r2, unsigned& r3, unsigned addr) {
    asm volatile("ldmatrix.sync.aligned.m8n8.x4.shared.b16 {%0,%1,%2,%3}, [%4];"
                 : "=r"(r0), "=r"(r1), "=r"(r2), "=r"(r3) : "r"(addr));
}
__device__ __forceinline__ void ldsm_x4_t(unsigned& r0, unsigned& r1,
                                          unsigned& r2, unsigned& r3, unsigned addr) {
    asm volatile("ldmatrix.sync.aligned.m8n8.x4.trans.shared.b16 {%0,%1,%2,%3}, [%4];"
                 : "=r"(r0), "=r"(r1), "=r"(r2), "=r"(r3) : "r"(addr));
}

__device__ __forceinline__ void mma16816(float* c, unsigned a0, unsigned a1,
                                         unsigned a2, unsigned a3,
                                         unsigned b0, unsigned b1) {
    asm volatile(
        "mma.sync.aligned.m16n8k16.row.col.f32.bf16.bf16.f32 "
        "{%0,%1,%2,%3},{%4,%5,%6,%7},{%8,%9},{%0,%1,%2,%3};"
        : "+f"(c[0]), "+f"(c[1]), "+f"(c[2]), "+f"(c[3])
        : "r"(a0), "r"(a1), "r"(a2), "r"(a3), "r"(b0), "r"(b1));
}

// ---------------------------------------------------------------------------
// Fused weight conversion
// ---------------------------------------------------------------------------
struct WcvtArgs {
    const float* src[8];
    int off[9];
};

__global__ void cvt_weights_kernel(WcvtArgs a, __nv_bfloat16* __restrict__ out)
{
    int i = blockIdx.x * 256 + threadIdx.x;
    if (i >= a.off[8]) return;
    int s = 0;
#pragma unroll
    for (int j = 1; j < 8; j++) s += (i >= a.off[j]);
    out[i] = __float2bfloat16(a.src[s][i - a.off[s]]);
}

// ---------------------------------------------------------------------------
// LayerNorm (standalone; only for the first LN on the fp32 input)
// ---------------------------------------------------------------------------
__global__ void ln_kernel(const float* __restrict__ x,
                          const float* __restrict__ g,
                          const float* __restrict__ b,
                          __nv_bfloat16* __restrict__ out)
{
    int row  = blockIdx.x * 8 + threadIdx.y;
    int lane = threadIdx.x;
    const float* xr = x + (size_t)row * C_DIM;
    float v[6];
    float s = 0.f;
#pragma unroll
    for (int i = 0; i < 6; i++) { v[i] = xr[lane + i * 32]; s += v[i]; }
#pragma unroll
    for (int o = 16; o; o >>= 1) s += __shfl_xor_sync(0xffffffffu, s, o);
    float mu = s * (1.0f / 192.0f);
    float vs = 0.f;
#pragma unroll
    for (int i = 0; i < 6; i++) { float d = v[i] - mu; vs += d * d; }
#pragma unroll
    for (int o = 16; o; o >>= 1) vs += __shfl_xor_sync(0xffffffffu, vs, o);
    float rstd = rsqrtf(vs * (1.0f / 192.0f) + 1e-5f);
    __nv_bfloat16* orow = out + (size_t)row * C_DIM;
#pragma unroll
    for (int i = 0; i < 6; i++) {
        int c = lane + i * 32;
        orow[c] = __float2bfloat16((v[i] - mu) * rstd * g[c] + b[c]);
    }
}

// ---------------------------------------------------------------------------
// bf16 GEMM (Round-7 proven mainloop): BM=128, BN=192, BK=32, 256 thr,
// 8 warps (4m x 2n), warp tile 32x96, 2-stage cp.async, static smem 46 KB.
// Optional fused LN over (residual-added) output rows (BN == full row).
// LN reduction buffer is ALIASED onto As smem (mainloop finished by then).
// ---------------------------------------------------------------------------
#define GBM 128
#define GBN 192
#define GBK 32
#define ASTRH 40
#define BSTRH 200
#define ASTAGE (GBM * ASTRH * 2)
#define BSTAGE (GBK * BSTRH * 2)

template<bool DOGELU, bool RES, bool OUTBF, bool DOLN>
__global__ __launch_bounds__(256, 1)
void gemm_bf16(const __nv_bfloat16* __restrict__ A,
               const __nv_bfloat16* __restrict__ B,
               const float* __restrict__ bias, const float* __restrict__ res,
               void* __restrict__ Cout,
               const float* __restrict__ lng, const float* __restrict__ lnb,
               __nv_bfloat16* __restrict__ lnout,
               int M, int N, int K)
{
    __shared__ __nv_bfloat16 As[2][GBM * ASTRH];
    __shared__ __nv_bfloat16 Bs[2][GBK * BSTRH];

    int tid = threadIdx.x;
    int bm = blockIdx.y * GBM;
    int bn = blockIdx.x * GBN;
    int wid = tid >> 5, lane = tid & 31;
    int wm = (wid & 3) * 32, wn = (wid >> 2) * 96;
    int g = lane >> 2, t = lane & 3;

    int ldrow = (lane & 7) + ((lane >> 3) & 1) * 8;
    int ldcol = (lane >> 4) * 8;

    unsigned sA0 = (unsigned)__cvta_generic_to_shared(&As[0][0]);
    unsigned sB0 = (unsigned)__cvta_generic_to_shared(&Bs[0][0]);
    unsigned aBase = sA0 + (unsigned)(((wm + ldrow) * ASTRH + ldcol) * 2);
    unsigned bBase = sB0 + (unsigned)((ldrow * BSTRH + wn + ldcol) * 2);

    float acc[2][12][4];
#pragma unroll
    for (int a = 0; a < 2; a++)
#pragma unroll
        for (int j = 0; j < 12; j++)
#pragma unroll
            for (int c = 0; c < 4; c++) acc[a][j][c] = 0.f;

    auto loadA = [&](int stage, int k0) {
#pragma unroll
        for (int l = 0; l < 2; l++) {
            int idx = tid + l * 256;
            int m = idx >> 2;
            int c = (idx & 3) * 8;
            cp_async16(&As[stage][m * ASTRH + c],
                       A + (size_t)(bm + m) * K + k0 + c);
        }
    };
    auto loadB = [&](int stage, int k0) {
#pragma unroll
        for (int l = 0; l < 3; l++) {
            int idx = tid + l * 256;
            if (idx < 768) {
                int r = idx / 24;
                int c = (idx % 24) * 8;
                cp_async16(&Bs[stage][r * BSTRH + c],
                           B + (size_t)(k0 + r) * N + bn + c);
            }
        }
    };

    int nk = K / GBK;
    loadA(0, 0); loadB(0, 0);
    asm volatile("cp.async.commit_group;");

    for (int kb = 0; kb < nk; kb++) {
        if (kb + 1 < nk) {
            loadA((kb + 1) & 1, (kb + 1) * GBK);
            loadB((kb + 1) & 1, (kb + 1) * GBK);
            asm volatile("cp.async.commit_group;");
            asm volatile("cp.async.wait_group 1;");
        } else {
            asm volatile("cp.async.wait_group 0;");
        }
        __syncthreads();

        unsigned aS = aBase + (kb & 1) * ASTAGE;
        unsigned bS = bBase + (kb & 1) * BSTAGE;
#pragma unroll
        for (int ks = 0; ks < 2; ks++) {
            unsigned af[2][4], bfr[6][4];
#pragma unroll
            for (int mt = 0; mt < 2; mt++)
                ldsm_x4(af[mt][0], af[mt][1], af[mt][2], af[mt][3],
                        aS + mt * (16 * ASTRH * 2) + ks * 32);
#pragma unroll
            for (int nt = 0; nt < 6; nt++)
                ldsm_x4_t(bfr[nt][0], bfr[nt][1], bfr[nt][2], bfr[nt][3],
                          bS + ks * (16 * BSTRH * 2) + nt * 32);
#pragma unroll
            for (int mt = 0; mt < 2; mt++)
#pragma unroll
                for (int nt = 0; nt < 6; nt++) {
                    mma16816(acc[mt][nt * 2],     af[mt][0], af[mt][1],
                             af[mt][2], af[mt][3], bfr[nt][0], bfr[nt][1]);
                    mma16816(acc[mt][nt * 2 + 1], af[mt][0], af[mt][1],
                             af[mt][2], af[mt][3], bfr[nt][2], bfr[nt][3]);
                }
        }
        __syncthreads();
    }

    // ---- epilogue: bias (+GELU) (+res) -> write; optional fused LN ----
    float rsum[4] = {0.f, 0.f, 0.f, 0.f};
    float rsq [4] = {0.f, 0.f, 0.f, 0.f};

#pragma unroll
    for (int mt = 0; mt < 2; mt++)
#pragma unroll
        for (int j = 0; j < 12; j++) {
            int col = bn + wn + j * 8 + 2 * t;
            float2 bv = *(const float2*)(bias + col);
#pragma unroll
            for (int hf = 0; hf < 2; hf++) {
                int row = bm + wm + mt * 16 + g + hf * 8;
                float x0 = acc[mt][j][hf * 2 + 0] + bv.x;
                float x1 = acc[mt][j][hf * 2 + 1] + bv.y;
                if (DOGELU) {
                    x0 = 0.5f * x0 * (1.0f + erff(x0 * 0.70710678118654752f));
                    x1 = 0.5f * x1 * (1.0f + erff(x1 * 0.70710678118654752f));
                }
                if (RES) {
                    float2 r = *(const float2*)(res + (size_t)row * N + col);
                    x0 += r.x; x1 += r.y;
                }
                if (OUTBF) {
                    __nv_bfloat162* p = (__nv_bfloat162*)
                        ((__nv_bfloat16*)Cout + (size_t)row * N + col);
                    *p = __floats2bfloat162_rn(x0, x1);
                } else {
                    *(float2*)((float*)Cout + (size_t)row * N + col)
                        = make_float2(x0, x1);
                }
                if (DOLN) {
                    acc[mt][j][hf * 2 + 0] = x0;
                    acc[mt][j][hf * 2 + 1] = x1;
                    rsum[mt * 2 + hf] += x0 + x1;
                    rsq [mt * 2 + hf] += x0 * x0 + x1 * x1;
                }
            }
        }

    if (DOLN) {
        // lnred[2 n-warps][128 rows] aliased onto As (mainloop is done)
        float2* lnred = reinterpret_cast<float2*>(&As[0][0]);
        int nw = wid >> 2;

#pragma unroll
        for (int i = 0; i < 4; i++) {
            rsum[i] += __shfl_xor_sync(0xffffffffu, rsum[i], 1);
            rsum[i] += __shfl_xor_sync(0xffffffffu, rsum[i], 2);
            rsq [i] += __shfl_xor_sync(0xffffffffu, rsq [i], 1);
            rsq [i] += __shfl_xor_sync(0xffffffffu, rsq [i], 2);
        }
        __syncthreads();    // ensure all mainloop smem reads done before alias
        if (t == 0) {
#pragma unroll
            for (int mt = 0; mt < 2; mt++)
#pragma unroll
                for (int hf = 0; hf < 2; hf++) {
                    int lrow = wm + mt * 16 + g + hf * 8;
                    lnred[nw * GBM + lrow] = make_float2(rsum[mt * 2 + hf],
                                                         rsq [mt * 2 + hf]);
                }
        }
        __syncthreads();

        float mu[4], rstd[4];
#pragma unroll
        for (int mt = 0; mt < 2; mt++)
#pragma unroll
            for (int hf = 0; hf < 2; hf++) {
                int lrow = wm + mt * 16 + g + hf * 8;
                float2 v0 = lnred[lrow];
                float2 v1 = lnred[GBM + lrow];
                float s = v0.x + v1.x, q = v0.y + v1.y;
                float m_ = s * (1.0f / 192.0f);
                float var = q * (1.0f / 192.0f) - m_ * m_;
                mu[mt * 2 + hf] = m_;
                rstd[mt * 2 + hf] = rsqrtf(var + 1e-5f);
            }

#pragma unroll
        for (int mt = 0; mt < 2; mt++)
#pragma unroll
            for (int j = 0; j < 12; j++) {
                int col = bn + wn + j * 8 + 2 * t;
                float2 gv = *(const float2*)(lng + col);
                float2 bv2 = *(const float2*)(lnb + col);
#pragma unroll
                for (int hf = 0; hf < 2; hf++) {
                    int row = bm + wm + mt * 16 + g + hf * 8;
                    float m_ = mu[mt * 2 + hf], rs = rstd[mt * 2 + hf];
                    float l0 = (acc[mt][j][hf * 2 + 0] - m_) * rs * gv.x + bv2.x;
                    float l1 = (acc[mt][j][hf * 2 + 1] - m_) * rs * gv.y + bv2.y;
                    *(__nv_bfloat162*)(lnout + (size_t)row * N + col)
                        = __floats2bfloat162_rn(l0, l1);
                }
            }
    }
}

// ---------------------------------------------------------------------------
// Tensor-core window attention (Round-7, unchanged)
// ---------------------------------------------------------------------------
__global__ __launch_bounds__(128)
void attn_tc_kernel(const __nv_bfloat16* __restrict__ qkv,
                    const float* __restrict__ rpb,
                    __nv_bfloat16* __restrict__ O, int shifted)
{
    __shared__ __nv_bfloat16 Qs[64 * 40];
    __shared__ __nv_bfloat16 Ks[64 * 40];
    __shared__ __nv_bfloat16 Vs[64 * 40];
    __shared__ float rpbs[2058];
    __shared__ int tok[64];
    __shared__ int regid[64];

    int tid = threadIdx.x;
    int wq = tid >> 5, lane = tid & 31;
    int g = lane >> 2, t = lane & 3;
    int win = blockIdx.x;
    int ws = win >> 8, wh = (win >> 4) & 15, ww = win & 15;

    if (tid < 64) {
        int i = tid >> 4, j = (tid >> 2) & 3, k = tid & 3;
        int cs = ws * 4 + i, ch = wh * 4 + j, cw = ww * 4 + k;
        int sg, hg, wg;
        if (shifted) { sg = (cs + 2) & 31; hg = (ch + 2) & 63; wg = (cw + 2) & 63; }
        else         { sg = cs;            hg = ch;            wg = cw; }
        tok[tid] = (sg * 64 + hg) * 64 + wg;
        int rs = cs < 28 ? 0 : (cs < 30 ? 1 : 2);
        int rh = ch < 60 ? 0 : (ch < 62 ? 1 : 2);
        int rw = cw < 60 ? 0 : (cw < 62 ? 1 : 2);
        regid[tid] = rs * 9 + rh * 3 + rw;
    }
    for (int i = tid; i < 2058; i += 128) rpbs[i] = rpb[i];
    __syncthreads();

    int r0 = wq * 16 + g;
    int r1 = r0 + 8;
    int i0 = r0 >> 4, j0 = (r0 >> 2) & 3, k0 = r0 & 3;
    int i1 = r1 >> 4, j1 = (r1 >> 2) & 3, k1 = r1 & 3;
    int reg0 = regid[r0], reg1 = regid[r1];
    size_t ob0 = (size_t)tok[r0] * C_DIM;
    size_t ob1 = (size_t)tok[r1] * C_DIM;

    int ldrow = (lane & 7) + ((lane >> 3) & 1) * 8;
    int ldcol = (lane >> 4) * 8;
    unsigned qB = (unsigned)__cvta_generic_to_shared(Qs)
                + (unsigned)(((wq * 16 + ldrow) * 40 + ldcol) * 2);
    unsigned kB = (unsigned)__cvta_generic_to_shared(Ks)
                + (unsigned)((ldrow * 40 + ldcol) * 2);
    unsigned vB = (unsigned)__cvta_generic_to_shared(Vs)
                + (unsigned)((ldrow * 40 + ldcol) * 2);

    const float scale = 0.17677669529663687f;

    for (int h = 0; h < 6; h++) {
#pragma unroll
        for (int l = 0; l < 2; l++) {
            int idx = tid + l * 128;
            int row = idx >> 2;
            int c = (idx & 3) * 8;
            const __nv_bfloat16* src = qkv + (size_t)tok[row] * QKV_DIM + h * 32 + c;
            cp_async16(&Qs[row * 40 + c], src);
            cp_async16(&Ks[row * 40 + c], src + 192);
            cp_async16(&Vs[row * 40 + c], src + 384);
        }
        asm volatile("cp.async.commit_group;");
        asm volatile("cp.async.wait_group 0;");
        __syncthreads();

        float s[8][4];
#pragma unroll
        for (int j = 0; j < 8; j++)
#pragma unroll
            for (int e = 0; e < 4; e++) s[j][e] = 0.f;

#pragma unroll
        for (int ks = 0; ks < 2; ks++) {
            unsigned a0, a1, a2, a3;
            ldsm_x4(a0, a1, a2, a3, qB + ks * 32);
#pragma unroll
            for (int nc = 0; nc < 4; nc++) {
                unsigned kr0, kr1, kr2, kr3;
                ldsm_x4(kr0, kr1, kr2, kr3, kB + nc * (16 * 80) + ks * 32);
                mma16816(s[nc * 2],     a0, a1, a2, a3, kr0, kr2);
                mma16816(s[nc * 2 + 1], a0, a1, a2, a3, kr1, kr3);
            }
        }

#pragma unroll
        for (int j = 0; j < 8; j++) {
            int cb = j * 8 + 2 * t;
#pragma unroll
            for (int e = 0; e < 4; e++) {
                int m = cb + (e & 1);
                int im = m >> 4, jm = (m >> 2) & 3, km = m & 3;
                float val;
                if (e < 2) {
                    int idx = (i0 - im + 3) * 49 + (j0 - jm + 3) * 7 + (k0 - km + 3);
                    val = s[j][e] * scale + rpbs[idx * 6 + h];
                    if (shifted && (reg0 != regid[m])) val -= 100.f;
                } else {
                    int idx = (i1 - im + 3) * 49 + (j1 - jm + 3) * 7 + (k1 - km + 3);
                    val = s[j][e] * scale + rpbs[idx * 6 + h];
                    if (shifted && (reg1 != regid[m])) val -= 100.f;
                }
                s[j][e] = val;
            }
        }

        float mx0 = -1e30f, mx1 = -1e30f;
#pragma unroll
        for (int j = 0; j < 8; j++) {
            mx0 = fmaxf(mx0, fmaxf(s[j][0], s[j][1]));
            mx1 = fmaxf(mx1, fmaxf(s[j][2], s[j][3]));
        }
        mx0 = fmaxf(mx0, __shfl_xor_sync(0xffffffffu, mx0, 1));
        mx0 = fmaxf(mx0, __shfl_xor_sync(0xffffffffu, mx0, 2));
        mx1 = fmaxf(mx1, __shfl_xor_sync(0xffffffffu, mx1, 1));
        mx1 = fmaxf(mx1, __shfl_xor_sync(0xffffffffu, mx1, 2));
        float sum0 = 0.f, sum1 = 0.f;
#pragma unroll
        for (int j = 0; j < 8; j++) {
            s[j][0] = __expf(s[j][0] - mx0);
            s[j][1] = __expf(s[j][1] - mx0);
            s[j][2] = __expf(s[j][2] - mx1);
            s[j][3] = __expf(s[j][3] - mx1);
            sum0 += s[j][0] + s[j][1];
            sum1 += s[j][2] + s[j][3];
        }
        sum0 += __shfl_xor_sync(0xffffffffu, sum0, 1);
        sum0 += __shfl_xor_sync(0xffffffffu, sum0, 2);
        sum1 += __shfl_xor_sync(0xffffffffu, sum1, 1);
        sum1 += __shfl_xor_sync(0xffffffffu, sum1, 2);
        float inv0 = 1.0f / sum0, inv1 = 1.0f / sum1;

        unsigned pa[4][4];
#pragma unroll
        for (int kk = 0; kk < 4; kk++) {
            __nv_bfloat162 p0 = __floats2bfloat162_rn(s[2 * kk][0],     s[2 * kk][1]);
            __nv_bfloat162 p1 = __floats2bfloat162_rn(s[2 * kk][2],     s[2 * kk][3]);
            __nv_bfloat162 p2 = __floats2bfloat162_rn(s[2 * kk + 1][0], s[2 * kk + 1][1]);
            __nv_bfloat162 p3 = __floats2bfloat162_rn(s[2 * kk + 1][2], s[2 * kk + 1][3]);
            pa[kk][0] = *(unsigned*)&p0;
            pa[kk][1] = *(unsigned*)&p1;
            pa[kk][2] = *(unsigned*)&p2;
            pa[kk][3] = *(unsigned*)&p3;
        }

        float o[4][4];
#pragma unroll
        for (int j = 0; j < 4; j++)
#pragma unroll
            for (int e = 0; e < 4; e++) o[j][e] = 0.f;

#pragma unroll
        for (int kk = 0; kk < 4; kk++) {
            unsigned v0, v1, v2, v3;
            ldsm_x4_t(v0, v1, v2, v3, vB + kk * (16 * 80));
            mma16816(o[0], pa[kk][0], pa[kk][1], pa[kk][2], pa[kk][3], v0, v1);
            mma16816(o[1], pa[kk][0], pa[kk][1], pa[kk][2], pa[kk][3], v2, v3);
            unsigned w0, w1, w2, w3;
            ldsm_x4_t(w0, w1, w2, w3, vB + kk * (16 * 80) + 32);
            mma16816(o[2], pa[kk][0], pa[kk][1], pa[kk][2], pa[kk][3], w0, w1);
            mma16816(o[3], pa[kk][0], pa[kk][1], pa[kk][2], pa[kk][3], w2, w3);
        }

#pragma unroll
        for (int nt = 0; nt < 4; nt++) {
            int col = h * 32 + nt * 8 + 2 * t;
            *(__nv_bfloat162*)(O + ob0 + col) =
                __floats2bfloat162_rn(o[nt][0] * inv0, o[nt][1] * inv0);
            *(__nv_bfloat162*)(O + ob1 + col) =
                __floats2bfloat162_rn(o[nt][2] * inv1, o[nt][3] * inv1);
        }
        __syncthreads();
    }
}

// ---------------------------------------------------------------------------
extern "C" void kernel_launch(void* const* d_in, const int* in_sizes, int n_in,
                              void* d_out, int out_size)
{
    (void)in_sizes; (void)n_in; (void)out_size;
    const float* x = (const float*)d_in[0];
    float* out = (float*)d_out;

    __nv_bfloat16 *bufA, *qkv, *obuf, *bufT, *wbf;
    cudaGetSymbolAddress((void**)&bufA, g_bufA);
    cudaGetSymbolAddress((void**)&qkv,  g_qkv);
    cudaGetSymbolAddress((void**)&obuf, g_obuf);
    cudaGetSymbolAddress((void**)&bufT, g_bufT);
    cudaGetSymbolAddress((void**)&wbf,  g_wbf);

    const int SZ_QW = C_DIM * QKV_DIM;
    const int SZ_PW = C_DIM * C_DIM;
    const int SZ_F1 = C_DIM * FF_DIM;
    const int SZ_F2 = FF_DIM * C_DIM;

    const int widx[8] = { 3, 6, 10, 12, 16, 19, 23, 25 };
    const int wsz [8] = { SZ_QW, SZ_PW, SZ_F1, SZ_F2, SZ_QW, SZ_PW, SZ_F1, SZ_F2 };

    WcvtArgs wa;
    int off = 0;
    __nv_bfloat16* wp[8];
    for (int i = 0; i < 8; i++) {
        wa.src[i] = (const float*)d_in[widx[i]];
        wa.off[i] = off;
        wp[i] = wbf + off;
        off += wsz[i];
    }
    wa.off[8] = off;
    cvt_weights_kernel<<<(off + 255) / 256, 256>>>(wa, wbf);

    const int MY = L_TOK / GBM;   // 1024
    dim3 lnBlk(32, 8);

    // ---------------- block 0 (unshifted) ----------------
    ln_kernel<<<L_TOK / 8, lnBlk>>>(x, (const float*)d_in[1],
                                    (const float*)d_in[2], bufA);
    gemm_bf16<false, false, true, false><<<dim3(QKV_DIM / GBN, MY), 256>>>(
        bufA, wp[0], (const float*)d_in[4], nullptr, qkv,
        nullptr, nullptr, nullptr, L_TOK, QKV_DIM, C_DIM);
    attn_tc_kernel<<<NWIN, 128>>>(qkv, (const float*)d_in[5], obuf, 0);
    // proj + residual(x) -> out (fp32) ; fused LN2 -> bufA
    gemm_bf16<false, true, false, true><<<dim3(C_DIM / GBN, MY), 256>>>(
        obuf, wp[1], (const float*)d_in[7], x, out,
        (const float*)d_in[8], (const float*)d_in[9], bufA,
        L_TOK, C_DIM, C_DIM);
    gemm_bf16<true, false, true, false><<<dim3(FF_DIM / GBN, MY), 256>>>(
        bufA, wp[2], (const float*)d_in[11], nullptr, bufT,
        nullptr, nullptr, nullptr, L_TOK, FF_DIM, C_DIM);
    // f2 + residual(out) -> out ; fused LN1 of block 1 -> bufA
    gemm_bf16<false, true, false, true><<<dim3(C_DIM / GBN, MY), 256>>>(
        bufT, wp[3], (const float*)d_in[13], out, out,
        (const float*)d_in[14], (const float*)d_in[15], bufA,
        L_TOK, C_DIM, FF_DIM);

    // ---------------- block 1 (shifted) ----------------
    gemm_bf16<false, false, true, false><<<dim3(QKV_DIM / GBN, MY), 256>>>(
        bufA, wp[4], (const float*)d_in[17], nullptr, qkv,
        nullptr, nullptr, nullptr, L_TOK, QKV_DIM, C_DIM);
    attn_tc_kernel<<<NWIN, 128>>>(qkv, (const float*)d_in[18], obuf, 1);
    gemm_bf16<false, true, false, true><<<dim3(C_DIM / GBN, MY), 256>>>(
        obuf, wp[5], (const float*)d_in[20], out, out,
        (const float*)d_in[21], (const float*)d_in[22], bufA,
        L_TOK, C_DIM, C_DIM);
    gemm_bf16<true, false, true, false><<<dim3(FF_DIM / GBN, MY), 256>>>(
        bufA, wp[6], (const float*)d_in[24], nullptr, bufT,
        nullptr, nullptr, nullptr, L_TOK, FF_DIM, C_DIM);
    gemm_bf16<false, true, false, false><<<dim3(C_DIM / GBN, MY), 256>>>(
        bufT, wp[7], (const float*)d_in[26], out, out,
        nullptr, nullptr, nullptr, L_TOK, C_DIM, FF_DIM);
}

// round 11
// speedup vs baseline: 1.1414x; 1.0045x over previous
#include <cuda_runtime.h>
#include <cuda_bf16.h>
#include <math.h>

#define L_TOK 131072
#define C_DIM 192
#define QKV_DIM 576
#define FF_DIM 768
#define NWIN 2048

typedef __nv_bfloat16 bf16;

// scratch (device globals)
__device__ bf16 g_bufA[(size_t)L_TOK * C_DIM];   // LN out (bf16)
__device__ bf16 g_qkv [(size_t)L_TOK * QKV_DIM]; // QKV (bf16)
__device__ bf16 g_obuf[(size_t)L_TOK * C_DIM];   // attn out (bf16)
__device__ bf16 g_bufT[(size_t)L_TOK * FF_DIM];  // MLP hidden (bf16)
__device__ bf16 g_wbf [884736];                  // bf16 weights [K,N]

__device__ __forceinline__ void cp_async16(void* smem, const void* gmem) {
    unsigned saddr = (unsigned)__cvta_generic_to_shared(smem);
    asm volatile("cp.async.cg.shared.global [%0], [%1], 16;\n" :: "r"(saddr), "l"(gmem));
}
__device__ __forceinline__ void ldsm_x4(unsigned& r0, unsigned& r1,
                                        unsigned& r2, unsigned& r3, unsigned addr) {
    asm volatile("ldmatrix.sync.aligned.m8n8.x4.shared.b16 {%0,%1,%2,%3}, [%4];"
                 : "=r"(r0), "=r"(r1), "=r"(r2), "=r"(r3) : "r"(addr));
}
__device__ __forceinline__ void ldsm_x4_t(unsigned& r0, unsigned& r1,
                                          unsigned& r2, unsigned& r3, unsigned addr) {
    asm volatile("ldmatrix.sync.aligned.m8n8.x4.trans.shared.b16 {%0,%1,%2,%3}, [%4];"
                 : "=r"(r0), "=r"(r1), "=r"(r2), "=r"(r3) : "r"(addr));
}
__device__ __forceinline__ void mma16816(float* c, unsigned a0, unsigned a1,
                                         unsigned a2, unsigned a3,
                                         unsigned b0, unsigned b1) {
    asm volatile(
        "mma.sync.aligned.m16n8k16.row.col.f32.bf16.bf16.f32 "
        "{%0,%1,%2,%3},{%4,%5,%6,%7},{%8,%9},{%0,%1,%2,%3};"
        : "+f"(c[0]), "+f"(c[1]), "+f"(c[2]), "+f"(c[3])
        : "r"(a0), "r"(a1), "r"(a2), "r"(a3), "r"(b0), "r"(b1));
}

// ---------------------------------------------------------------------------
// Fused weight conversion (plain [K,N] fp32 -> bf16)
// ---------------------------------------------------------------------------
struct WcvtArgs {
    const float* src[8];
    int off[9];
};

__global__ void cvt_weights_kernel(WcvtArgs a, bf16* __restrict__ out)
{
    int i = blockIdx.x * 256 + threadIdx.x;
    if (i >= a.off[8]) return;
    int s = 0;
#pragma unroll
    for (int j = 1; j < 8; j++) s += (i >= a.off[j]);
    out[i] = __float2bfloat16(a.src[s][i - a.off[s]]);
}

// ---------------------------------------------------------------------------
// LayerNorm, one row per warp; bf16 output
// ---------------------------------------------------------------------------
__global__ void ln_kernel(const float* __restrict__ x,
                          const float* __restrict__ g,
                          const float* __restrict__ b,
                          bf16* __restrict__ out)
{
    int row  = blockIdx.x * 8 + threadIdx.y;
    int lane = threadIdx.x;
    const float* xr = x + (size_t)row * C_DIM;
    float v[6];
    float s = 0.f;
#pragma unroll
    for (int i = 0; i < 6; i++) { v[i] = xr[lane + i * 32]; s += v[i]; }
#pragma unroll
    for (int o = 16; o; o >>= 1) s += __shfl_xor_sync(0xffffffffu, s, o);
    float mu = s * (1.0f / 192.0f);
    float vs = 0.f;
#pragma unroll
    for (int i = 0; i < 6; i++) { float d = v[i] - mu; vs += d * d; }
#pragma unroll
    for (int o = 16; o; o >>= 1) vs += __shfl_xor_sync(0xffffffffu, vs, o);
    float rstd = rsqrtf(vs * (1.0f / 192.0f) + 1e-5f);
    bf16* orow = out + (size_t)row * C_DIM;
#pragma unroll
    for (int i = 0; i < 6; i++) {
        int c = lane + i * 32;
        orow[c] = __float2bfloat16((v[i] - mu) * rstd * g[c] + b[c]);
    }
}

// ---------------------------------------------------------------------------
// bf16 GEMM: BM=128, BN=192, BK=32. 384 thr, 12 warps (4m x 3n),
// warp tile 32x64 (acc 64 regs). 3-stage cp.async pipeline, dynamic smem.
// ---------------------------------------------------------------------------
#define GBM 128
#define GBN 192
#define GBK 32
#define ASTRH 40
#define BSTRH 200
#define ABYTES (GBM * ASTRH * 2)     // 10240
#define BBYTES (GBK * BSTRH * 2)     // 12800
#define STAGEB (ABYTES + BBYTES)     // 23040
#define NSTAGE 3
#define GSMEM  (STAGEB * NSTAGE)     // 69120

template<bool DOGELU, bool RES, bool OUTBF>
__global__ __launch_bounds__(384, 1)
void gemm_bf16(const bf16* __restrict__ A, const bf16* __restrict__ B,
               const float* __restrict__ bias, const float* __restrict__ res,
               void* __restrict__ Cout, int M, int N, int K)
{
    extern __shared__ char smem[];

    int tid = threadIdx.x;
    int bm = blockIdx.y * GBM;
    int bn = blockIdx.x * GBN;
    int wid = tid >> 5, lane = tid & 31;
    int wm = (wid & 3) * 32, wn = (wid >> 2) * 64;
    int g = lane >> 2, t = lane & 3;

    int ldrow = (lane & 7) + ((lane >> 3) & 1) * 8;
    int ldcol = (lane >> 4) * 8;

    unsigned s0 = (unsigned)__cvta_generic_to_shared(smem);
    unsigned aBase = s0 + (unsigned)(((wm + ldrow) * ASTRH + ldcol) * 2);
    unsigned bBase = s0 + (unsigned)(ABYTES + (ldrow * BSTRH + wn + ldcol) * 2);

    float acc[2][8][4];
#pragma unroll
    for (int a = 0; a < 2; a++)
#pragma unroll
        for (int j = 0; j < 8; j++)
#pragma unroll
            for (int c = 0; c < 4; c++) acc[a][j][c] = 0.f;

    auto loadA = [&](int stage, int k0) {
        // 128 rows x 4 chunks(8 bf16) = 512
#pragma unroll
        for (int l = 0; l < 2; l++) {
            int idx = tid + l * 384;
            if (idx < 512) {
                int m = idx >> 2;
                int c = (idx & 3) * 8;
                cp_async16(smem + stage * STAGEB + (m * ASTRH + c) * 2,
                           A + (size_t)(bm + m) * K + k0 + c);
            }
        }
    };
    auto loadB = [&](int stage, int k0) {
        // 32 rows x 24 chunks = 768 = 2 per thread
#pragma unroll
        for (int l = 0; l < 2; l++) {
            int idx = tid + l * 384;
            int r = idx / 24;
            int c = (idx % 24) * 8;
            cp_async16(smem + stage * STAGEB + ABYTES + (r * BSTRH + c) * 2,
                       B + (size_t)(k0 + r) * N + bn + c);
        }
    };

    int nk = K / GBK;
    loadA(0, 0); loadB(0, 0);
    asm volatile("cp.async.commit_group;");
    loadA(1, GBK); loadB(1, GBK);
    asm volatile("cp.async.commit_group;");

    for (int kb = 0; kb < nk; kb++) {
        if (kb + 2 < nk) {
            loadA((kb + 2) % NSTAGE, (kb + 2) * GBK);
            loadB((kb + 2) % NSTAGE, (kb + 2) * GBK);
            asm volatile("cp.async.commit_group;");
            asm volatile("cp.async.wait_group 2;");
        } else if (kb + 1 < nk) {
            asm volatile("cp.async.wait_group 1;");
        } else {
            asm volatile("cp.async.wait_group 0;");
        }
        __syncthreads();

        int st = kb % NSTAGE;
        unsigned aS = aBase + st * STAGEB;
        unsigned bS = bBase + st * STAGEB;
#pragma unroll
        for (int ks = 0; ks < 2; ks++) {
            unsigned af[2][4], bfr[4][4];
#pragma unroll
            for (int mt = 0; mt < 2; mt++)
                ldsm_x4(af[mt][0], af[mt][1], af[mt][2], af[mt][3],
                        aS + mt * (16 * ASTRH * 2) + ks * 32);
#pragma unroll
            for (int nt = 0; nt < 4; nt++)
                ldsm_x4_t(bfr[nt][0], bfr[nt][1], bfr[nt][2], bfr[nt][3],
                          bS + ks * (16 * BSTRH * 2) + nt * 32);
#pragma unroll
            for (int mt = 0; mt < 2; mt++)
#pragma unroll
                for (int nt = 0; nt < 4; nt++) {
                    mma16816(acc[mt][nt * 2],     af[mt][0], af[mt][1],
                             af[mt][2], af[mt][3], bfr[nt][0], bfr[nt][1]);
                    mma16816(acc[mt][nt * 2 + 1], af[mt][0], af[mt][1],
                             af[mt][2], af[mt][3], bfr[nt][2], bfr[nt][3]);
                }
        }
        __syncthreads();
    }

#pragma unroll
    for (int mt = 0; mt < 2; mt++)
#pragma unroll
        for (int j = 0; j < 8; j++) {
            int col = bn + wn + j * 8 + 2 * t;
            float2 bv = *(const float2*)(bias + col);
#pragma unroll
            for (int hf = 0; hf < 2; hf++) {
                int row = bm + wm + mt * 16 + g + hf * 8;
                float x0 = acc[mt][j][hf * 2 + 0] + bv.x;
                float x1 = acc[mt][j][hf * 2 + 1] + bv.y;
                if (DOGELU) {
                    x0 = 0.5f * x0 * (1.0f + erff(x0 * 0.70710678118654752f));
                    x1 = 0.5f * x1 * (1.0f + erff(x1 * 0.70710678118654752f));
                }
                if (RES) {
                    float2 r = *(const float2*)(res + (size_t)row * N + col);
                    x0 += r.x; x1 += r.y;
                }
                if (OUTBF) {
                    __nv_bfloat162* p = (__nv_bfloat162*)
                        ((bf16*)Cout + (size_t)row * N + col);
                    *p = __floats2bfloat162_rn(x0, x1);
                } else {
                    *(float2*)((float*)Cout + (size_t)row * N + col)
                        = make_float2(x0, x1);
                }
            }
        }
}

// ---------------------------------------------------------------------------
// Tensor-core window attention (Round-7, unchanged)
// ---------------------------------------------------------------------------
__global__ __launch_bounds__(128)
void attn_tc_kernel(const bf16* __restrict__ qkv,
                    const float* __restrict__ rpb,
                    bf16* __restrict__ O, int shifted)
{
    __shared__ bf16 Qs[64 * 40];
    __shared__ bf16 Ks[64 * 40];
    __shared__ bf16 Vs[64 * 40];
    __shared__ float rpbs[2058];
    __shared__ int tok[64];
    __shared__ int regid[64];

    int tid = threadIdx.x;
    int wq = tid >> 5, lane = tid & 31;
    int g = lane >> 2, t = lane & 3;
    int win = blockIdx.x;
    int ws = win >> 8, wh = (win >> 4) & 15, ww = win & 15;

    if (tid < 64) {
        int i = tid >> 4, j = (tid >> 2) & 3, k = tid & 3;
        int cs = ws * 4 + i, ch = wh * 4 + j, cw = ww * 4 + k;
        int sg, hg, wg;
        if (shifted) { sg = (cs + 2) & 31; hg = (ch + 2) & 63; wg = (cw + 2) & 63; }
        else         { sg = cs;            hg = ch;            wg = cw; }
        tok[tid] = (sg * 64 + hg) * 64 + wg;
        int rs = cs < 28 ? 0 : (cs < 30 ? 1 : 2);
        int rh = ch < 60 ? 0 : (ch < 62 ? 1 : 2);
        int rw = cw < 60 ? 0 : (cw < 62 ? 1 : 2);
        regid[tid] = rs * 9 + rh * 3 + rw;
    }
    for (int i = tid; i < 2058; i += 128) rpbs[i] = rpb[i];
    __syncthreads();

    int r0 = wq * 16 + g;
    int r1 = r0 + 8;
    int i0 = r0 >> 4, j0 = (r0 >> 2) & 3, k0 = r0 & 3;
    int i1 = r1 >> 4, j1 = (r1 >> 2) & 3, k1 = r1 & 3;
    int reg0 = regid[r0], reg1 = regid[r1];
    size_t ob0 = (size_t)tok[r0] * C_DIM;
    size_t ob1 = (size_t)tok[r1] * C_DIM;

    int ldrow = (lane & 7) + ((lane >> 3) & 1) * 8;
    int ldcol = (lane >> 4) * 8;
    unsigned qB = (unsigned)__cvta_generic_to_shared(Qs)
                + (unsigned)(((wq * 16 + ldrow) * 40 + ldcol) * 2);
    unsigned kB = (unsigned)__cvta_generic_to_shared(Ks)
                + (unsigned)((ldrow * 40 + ldcol) * 2);
    unsigned vB = (unsigned)__cvta_generic_to_shared(Vs)
                + (unsigned)((ldrow * 40 + ldcol) * 2);

    const float scale = 0.17677669529663687f;

    for (int h = 0; h < 6; h++) {
#pragma unroll
        for (int l = 0; l < 2; l++) {
            int idx = tid + l * 128;
            int row = idx >> 2;
            int c = (idx & 3) * 8;
            const bf16* src = qkv + (size_t)tok[row] * QKV_DIM + h * 32 + c;
            cp_async16(&Qs[row * 40 + c], src);
            cp_async16(&Ks[row * 40 + c], src + 192);
            cp_async16(&Vs[row * 40 + c], src + 384);
        }
        asm volatile("cp.async.commit_group;");
        asm volatile("cp.async.wait_group 0;");
        __syncthreads();

        float s[8][4];
#pragma unroll
        for (int j = 0; j < 8; j++)
#pragma unroll
            for (int e = 0; e < 4; e++) s[j][e] = 0.f;

#pragma unroll
        for (int ks = 0; ks < 2; ks++) {
            unsigned a0, a1, a2, a3;
            ldsm_x4(a0, a1, a2, a3, qB + ks * 32);
#pragma unroll
            for (int nc = 0; nc < 4; nc++) {
                unsigned kr0, kr1, kr2, kr3;
                ldsm_x4(kr0, kr1, kr2, kr3, kB + nc * (16 * 80) + ks * 32);
                mma16816(s[nc * 2],     a0, a1, a2, a3, kr0, kr2);
                mma16816(s[nc * 2 + 1], a0, a1, a2, a3, kr1, kr3);
            }
        }

#pragma unroll
        for (int j = 0; j < 8; j++) {
            int cb = j * 8 + 2 * t;
#pragma unroll
            for (int e = 0; e < 4; e++) {
                int m = cb + (e & 1);
                int im = m >> 4, jm = (m >> 2) & 3, km = m & 3;
                float val;
                if (e < 2) {
                    int idx = (i0 - im + 3) * 49 + (j0 - jm + 3) * 7 + (k0 - km + 3);
                    val = s[j][e] * scale + rpbs[idx * 6 + h];
                    if (shifted && (reg0 != regid[m])) val -= 100.f;
                } else {
                    int idx = (i1 - im + 3) * 49 + (j1 - jm + 3) * 7 + (k1 - km + 3);
                    val = s[j][e] * scale + rpbs[idx * 6 + h];
                    if (shifted && (reg1 != regid[m])) val -= 100.f;
                }
                s[j][e] = val;
            }
        }

        float mx0 = -1e30f, mx1 = -1e30f;
#pragma unroll
        for (int j = 0; j < 8; j++) {
            mx0 = fmaxf(mx0, fmaxf(s[j][0], s[j][1]));
            mx1 = fmaxf(mx1, fmaxf(s[j][2], s[j][3]));
        }
        mx0 = fmaxf(mx0, __shfl_xor_sync(0xffffffffu, mx0, 1));
        mx0 = fmaxf(mx0, __shfl_xor_sync(0xffffffffu, mx0, 2));
        mx1 = fmaxf(mx1, __shfl_xor_sync(0xffffffffu, mx1, 1));
        mx1 = fmaxf(mx1, __shfl_xor_sync(0xffffffffu, mx1, 2));
        float sum0 = 0.f, sum1 = 0.f;
#pragma unroll
        for (int j = 0; j < 8; j++) {
            s[j][0] = __expf(s[j][0] - mx0);
            s[j][1] = __expf(s[j][1] - mx0);
            s[j][2] = __expf(s[j][2] - mx1);
            s[j][3] = __expf(s[j][3] - mx1);
            sum0 += s[j][0] + s[j][1];
            sum1 += s[j][2] + s[j][3];
        }
        sum0 += __shfl_xor_sync(0xffffffffu, sum0, 1);
        sum0 += __shfl_xor_sync(0xffffffffu, sum0, 2);
        sum1 += __shfl_xor_sync(0xffffffffu, sum1, 1);
        sum1 += __shfl_xor_sync(0xffffffffu, sum1, 2);
        float inv0 = 1.0f / sum0, inv1 = 1.0f / sum1;

        unsigned pa[4][4];
#pragma unroll
        for (int kk = 0; kk < 4; kk++) {
            __nv_bfloat162 p0 = __floats2bfloat162_rn(s[2 * kk][0],     s[2 * kk][1]);
            __nv_bfloat162 p1 = __floats2bfloat162_rn(s[2 * kk][2],     s[2 * kk][3]);
            __nv_bfloat162 p2 = __floats2bfloat162_rn(s[2 * kk + 1][0], s[2 * kk + 1][1]);
            __nv_bfloat162 p3 = __floats2bfloat162_rn(s[2 * kk + 1][2], s[2 * kk + 1][3]);
            pa[kk][0] = *(unsigned*)&p0;
            pa[kk][1] = *(unsigned*)&p1;
            pa[kk][2] = *(unsigned*)&p2;
            pa[kk][3] = *(unsigned*)&p3;
        }

        float o[4][4];
#pragma unroll
        for (int j = 0; j < 4; j++)
#pragma unroll
            for (int e = 0; e < 4; e++) o[j][e] = 0.f;

#pragma unroll
        for (int kk = 0; kk < 4; kk++) {
            unsigned v0, v1, v2, v3;
            ldsm_x4_t(v0, v1, v2, v3, vB + kk * (16 * 80));
            mma16816(o[0], pa[kk][0], pa[kk][1], pa[kk][2], pa[kk][3], v0, v1);
            mma16816(o[1], pa[kk][0], pa[kk][1], pa[kk][2], pa[kk][3], v2, v3);
            unsigned w0, w1, w2, w3;
            ldsm_x4_t(w0, w1, w2, w3, vB + kk * (16 * 80) + 32);
            mma16816(o[2], pa[kk][0], pa[kk][1], pa[kk][2], pa[kk][3], w0, w1);
            mma16816(o[3], pa[kk][0], pa[kk][1], pa[kk][2], pa[kk][3], w2, w3);
        }

#pragma unroll
        for (int nt = 0; nt < 4; nt++) {
            int col = h * 32 + nt * 8 + 2 * t;
            *(__nv_bfloat162*)(O + ob0 + col) =
                __floats2bfloat162_rn(o[nt][0] * inv0, o[nt][1] * inv0);
            *(__nv_bfloat162*)(O + ob1 + col) =
                __floats2bfloat162_rn(o[nt][2] * inv1, o[nt][3] * inv1);
        }
        __syncthreads();
    }
}

// ---------------------------------------------------------------------------
static void run_block(const float* Xin, float* Xout,
                      const float* g1, const float* b1,
                      const bf16* qw, const float* qb, const float* rpb,
                      const bf16* pw, const float* pb,
                      const float* g2, const float* b2,
                      const bf16* f1w, const float* f1b,
                      const bf16* f2w, const float* f2b,
                      int shifted,
                      bf16* bufA, bf16* qkv, bf16* obuf, bf16* bufT)
{
    dim3 lnBlk(32, 8);
    int lnGrid = L_TOK / 8;

    ln_kernel<<<lnGrid, lnBlk>>>(Xin, g1, b1, bufA);
    gemm_bf16<false, false, true><<<dim3(QKV_DIM / GBN, L_TOK / GBM), 384, GSMEM>>>(
        bufA, qw, qb, nullptr, qkv, L_TOK, QKV_DIM, C_DIM);
    attn_tc_kernel<<<NWIN, 128>>>(qkv, rpb, obuf, shifted);
    gemm_bf16<false, true, false><<<dim3(C_DIM / GBN, L_TOK / GBM), 384, GSMEM>>>(
        obuf, pw, pb, Xin, Xout, L_TOK, C_DIM, C_DIM);
    ln_kernel<<<lnGrid, lnBlk>>>(Xout, g2, b2, bufA);
    gemm_bf16<true, false, true><<<dim3(FF_DIM / GBN, L_TOK / GBM), 384, GSMEM>>>(
        bufA, f1w, f1b, nullptr, bufT, L_TOK, FF_DIM, C_DIM);
    gemm_bf16<false, true, false><<<dim3(C_DIM / GBN, L_TOK / GBM), 384, GSMEM>>>(
        bufT, f2w, f2b, Xout, Xout, L_TOK, C_DIM, FF_DIM);
}

extern "C" void kernel_launch(void* const* d_in, const int* in_sizes, int n_in,
                              void* d_out, int out_size)
{
    (void)in_sizes; (void)n_in; (void)out_size;
    const float* x = (const float*)d_in[0];
    float* out = (float*)d_out;

    bf16 *bufA, *qkv, *obuf, *bufT, *wbf;
    cudaGetSymbolAddress((void**)&bufA, g_bufA);
    cudaGetSymbolAddress((void**)&qkv,  g_qkv);
    cudaGetSymbolAddress((void**)&obuf, g_obuf);
    cudaGetSymbolAddress((void**)&bufT, g_bufT);
    cudaGetSymbolAddress((void**)&wbf,  g_wbf);

    cudaFuncSetAttribute(gemm_bf16<false, false, true>,
                         cudaFuncAttributeMaxDynamicSharedMemorySize, GSMEM);
    cudaFuncSetAttribute(gemm_bf16<false, true, false>,
                         cudaFuncAttributeMaxDynamicSharedMemorySize, GSMEM);
    cudaFuncSetAttribute(gemm_bf16<true, false, true>,
                         cudaFuncAttributeMaxDynamicSharedMemorySize, GSMEM);

    const int SZ_QW = C_DIM * QKV_DIM;
    const int SZ_PW = C_DIM * C_DIM;
    const int SZ_F1 = C_DIM * FF_DIM;
    const int SZ_F2 = FF_DIM * C_DIM;

    const int widx[8] = { 3, 6, 10, 12, 16, 19, 23, 25 };
    const int wsz [8] = { SZ_QW, SZ_PW, SZ_F1, SZ_F2, SZ_QW, SZ_PW, SZ_F1, SZ_F2 };

    WcvtArgs wa;
    int off = 0;
    bf16* wp[8];
    for (int i = 0; i < 8; i++) {
        wa.src[i] = (const float*)d_in[widx[i]];
        wa.off[i] = off;
        wp[i] = wbf + off;
        off += wsz[i];
    }
    wa.off[8] = off;
    cvt_weights_kernel<<<(off + 255) / 256, 256>>>(wa, wbf);

    run_block(x, out,
              (const float*)d_in[1],  (const float*)d_in[2],
              wp[0],                  (const float*)d_in[4],  (const float*)d_in[5],
              wp[1],                  (const float*)d_in[7],
              (const float*)d_in[8],  (const float*)d_in[9],
              wp[2],                  (const float*)d_in[11],
              wp[3],                  (const float*)d_in[13],
              0, bufA, qkv, obuf, bufT);

    run_block(out, out,
              (const float*)d_in[14], (const float*)d_in[15],
              wp[4],                  (const float*)d_in[17], (const float*)d_in[18],
              wp[5],                  (const float*)d_in[20],
              (const float*)d_in[21], (const float*)d_in[22],
              wp[6],                  (const float*)d_in[24],
              wp[7],                  (const float*)d_in[26],
              1, bufA, qkv, obuf, bufT);
}

// round 12
// speedup vs baseline: 1.2337x; 1.0809x over previous
#include <cuda_runtime.h>
#include <cuda_bf16.h>
#include <math.h>

#define L_TOK 131072
#define C_DIM 192
#define QKV_DIM 576
#define FF_DIM 768
#define NWIN 2048

typedef __nv_bfloat16 bf16;

// scratch (device globals)
__device__ bf16 g_bufA[(size_t)L_TOK * C_DIM];   // LN out (bf16)
__device__ bf16 g_qkv [(size_t)L_TOK * QKV_DIM]; // QKV (bf16)
__device__ bf16 g_obuf[(size_t)L_TOK * C_DIM];   // attn out (bf16)
__device__ bf16 g_bufT[(size_t)L_TOK * FF_DIM];  // MLP hidden (bf16)
__device__ bf16 g_wbf [884736];                  // bf16 weights [K,N]

__device__ __forceinline__ void cp_async16(void* smem, const void* gmem) {
    unsigned saddr = (unsigned)__cvta_generic_to_shared(smem);
    asm volatile("cp.async.cg.shared.global [%0], [%1], 16;\n" :: "r"(saddr), "l"(gmem));
}
__device__ __forceinline__ void ldsm_x4(unsigned& r0, unsigned& r1,
                                        unsigned& r2, unsigned& r3, unsigned addr) {
    asm volatile("ldmatrix.sync.aligned.m8n8.x4.shared.b16 {%0,%1,%2,%3}, [%4];"
                 : "=r"(r0), "=r"(r1), "=r"(r2), "=r"(r3) : "r"(addr));
}
__device__ __forceinline__ void ldsm_x4_t(unsigned& r0, unsigned& r1,
                                          unsigned& r2, unsigned& r3, unsigned addr) {
    asm volatile("ldmatrix.sync.aligned.m8n8.x4.trans.shared.b16 {%0,%1,%2,%3}, [%4];"
                 : "=r"(r0), "=r"(r1), "=r"(r2), "=r"(r3) : "r"(addr));
}
__device__ __forceinline__ void mma16816(float* c, unsigned a0, unsigned a1,
                                         unsigned a2, unsigned a3,
                                         unsigned b0, unsigned b1) {
    asm volatile(
        "mma.sync.aligned.m16n8k16.row.col.f32.bf16.bf16.f32 "
        "{%0,%1,%2,%3},{%4,%5,%6,%7},{%8,%9},{%0,%1,%2,%3};"
        : "+f"(c[0]), "+f"(c[1]), "+f"(c[2]), "+f"(c[3])
        : "r"(a0), "r"(a1), "r"(a2), "r"(a3), "r"(b0), "r"(b1));
}

// ---------------------------------------------------------------------------
// Fused weight conversion
// ---------------------------------------------------------------------------
struct WcvtArgs {
    const float* src[8];
    int off[9];
};

__global__ void cvt_weights_kernel(WcvtArgs a, bf16* __restrict__ out)
{
    int i = blockIdx.x * 256 + threadIdx.x;
    if (i >= a.off[8]) return;
    int s = 0;
#pragma unroll
    for (int j = 1; j < 8; j++) s += (i >= a.off[j]);
    out[i] = __float2bfloat16(a.src[s][i - a.off[s]]);
}

// ---------------------------------------------------------------------------
// LayerNorm, one row per warp; bf16 output
// ---------------------------------------------------------------------------
__global__ void ln_kernel(const float* __restrict__ x,
                          const float* __restrict__ g,
                          const float* __restrict__ b,
                          bf16* __restrict__ out)
{
    int row  = blockIdx.x * 8 + threadIdx.y;
    int lane = threadIdx.x;
    const float* xr = x + (size_t)row * C_DIM;
    float v[6];
    float s = 0.f;
#pragma unroll
    for (int i = 0; i < 6; i++) { v[i] = xr[lane + i * 32]; s += v[i]; }
#pragma unroll
    for (int o = 16; o; o >>= 1) s += __shfl_xor_sync(0xffffffffu, s, o);
    float mu = s * (1.0f / 192.0f);
    float vs = 0.f;
#pragma unroll
    for (int i = 0; i < 6; i++) { float d = v[i] - mu; vs += d * d; }
#pragma unroll
    for (int o = 16; o; o >>= 1) vs += __shfl_xor_sync(0xffffffffu, vs, o);
    float rstd = rsqrtf(vs * (1.0f / 192.0f) + 1e-5f);
    bf16* orow = out + (size_t)row * C_DIM;
#pragma unroll
    for (int i = 0; i < 6; i++) {
        int c = lane + i * 32;
        orow[c] = __float2bfloat16((v[i] - mu) * rstd * g[c] + b[c]);
    }
}

// ---------------------------------------------------------------------------
// bf16 GEMM: BM=128, BN=192, BK=64. 256 thr, 8 warps (4m x 2n),
// warp tile 32x96. 2-stage cp.async pipeline, dynamic smem 88 KB.
// Halved sync count vs BK=32; 4 independent k-steps per stage.
// ---------------------------------------------------------------------------
#define GBM 128
#define GBN 192
#define GBK 64
#define ASTRH 72                      // 64 + 8 pad (bf16)
#define BSTRH 200                     // 192 + 8 pad (bf16)
#define ABYTES (GBM * ASTRH * 2)      // 18432
#define BBYTES (GBK * BSTRH * 2)      // 25600
#define STAGEB (ABYTES + BBYTES)      // 44032
#define GSMEM  (2 * STAGEB)           // 88064

template<bool DOGELU, bool RES, bool OUTBF>
__global__ __launch_bounds__(256, 1)
void gemm_bf16(const bf16* __restrict__ A, const bf16* __restrict__ B,
               const float* __restrict__ bias, const float* __restrict__ res,
               void* __restrict__ Cout, int M, int N, int K)
{
    extern __shared__ char smem[];

    int tid = threadIdx.x;
    int bm = blockIdx.y * GBM;
    int bn = blockIdx.x * GBN;
    int wid = tid >> 5, lane = tid & 31;
    int wm = (wid & 3) * 32, wn = (wid >> 2) * 96;
    int g = lane >> 2, t = lane & 3;

    int ldrow = (lane & 7) + ((lane >> 3) & 1) * 8;
    int ldcol = (lane >> 4) * 8;

    unsigned s0 = (unsigned)__cvta_generic_to_shared(smem);
    unsigned aBase = s0 + (unsigned)(((wm + ldrow) * ASTRH + ldcol) * 2);
    unsigned bBase = s0 + (unsigned)(ABYTES + (ldrow * BSTRH + wn + ldcol) * 2);

    float acc[2][12][4];
#pragma unroll
    for (int a = 0; a < 2; a++)
#pragma unroll
        for (int j = 0; j < 12; j++)
#pragma unroll
            for (int c = 0; c < 4; c++) acc[a][j][c] = 0.f;

    auto loadA = [&](int stage, int k0) {
        // 128 rows x 8 chunks(8 bf16) = 1024 -> 4 per thread
#pragma unroll
        for (int l = 0; l < 4; l++) {
            int idx = tid + l * 256;
            int m = idx >> 3;
            int c = (idx & 7) * 8;
            cp_async16(smem + stage * STAGEB + (m * ASTRH + c) * 2,
                       A + (size_t)(bm + m) * K + k0 + c);
        }
    };
    auto loadB = [&](int stage, int k0) {
        // 64 rows x 24 chunks = 1536 -> 6 per thread
#pragma unroll
        for (int l = 0; l < 6; l++) {
            int idx = tid + l * 256;
            int r = idx / 24;
            int c = (idx % 24) * 8;
            cp_async16(smem + stage * STAGEB + ABYTES + (r * BSTRH + c) * 2,
                       B + (size_t)(k0 + r) * N + bn + c);
        }
    };

    int nk = K / GBK;
    loadA(0, 0); loadB(0, 0);
    asm volatile("cp.async.commit_group;");
    if (nk > 1) { loadA(1, GBK); loadB(1, GBK); }
    asm volatile("cp.async.commit_group;");

    for (int kb = 0; kb < nk; kb++) {
        if (kb + 1 < nk) { asm volatile("cp.async.wait_group 1;"); }
        else             { asm volatile("cp.async.wait_group 0;"); }
        __syncthreads();

        int st = kb & 1;
        unsigned aS = aBase + st * STAGEB;
        unsigned bS = bBase + st * STAGEB;
#pragma unroll
        for (int ks = 0; ks < 4; ks++) {
            unsigned af[2][4], bfr[6][4];
#pragma unroll
            for (int mt = 0; mt < 2; mt++)
                ldsm_x4(af[mt][0], af[mt][1], af[mt][2], af[mt][3],
                        aS + mt * (16 * ASTRH * 2) + ks * 32);
#pragma unroll
            for (int nt = 0; nt < 6; nt++)
                ldsm_x4_t(bfr[nt][0], bfr[nt][1], bfr[nt][2], bfr[nt][3],
                          bS + ks * (16 * BSTRH * 2) + nt * 32);
#pragma unroll
            for (int mt = 0; mt < 2; mt++)
#pragma unroll
                for (int nt = 0; nt < 6; nt++) {
                    mma16816(acc[mt][nt * 2],     af[mt][0], af[mt][1],
                             af[mt][2], af[mt][3], bfr[nt][0], bfr[nt][1]);
                    mma16816(acc[mt][nt * 2 + 1], af[mt][0], af[mt][1],
                             af[mt][2], af[mt][3], bfr[nt][2], bfr[nt][3]);
                }
        }
        __syncthreads();

        if (kb + 2 < nk) {
            loadA(kb & 1, (kb + 2) * GBK);
            loadB(kb & 1, (kb + 2) * GBK);
        }
        asm volatile("cp.async.commit_group;");
    }

#pragma unroll
    for (int mt = 0; mt < 2; mt++)
#pragma unroll
        for (int j = 0; j < 12; j++) {
            int col = bn + wn + j * 8 + 2 * t;
            float2 bv = *(const float2*)(bias + col);
#pragma unroll
            for (int hf = 0; hf < 2; hf++) {
                int row = bm + wm + mt * 16 + g + hf * 8;
                float x0 = acc[mt][j][hf * 2 + 0] + bv.x;
                float x1 = acc[mt][j][hf * 2 + 1] + bv.y;
                if (DOGELU) {
                    x0 = 0.5f * x0 * (1.0f + erff(x0 * 0.70710678118654752f));
                    x1 = 0.5f * x1 * (1.0f + erff(x1 * 0.70710678118654752f));
                }
                if (RES) {
                    float2 r = *(const float2*)(res + (size_t)row * N + col);
                    x0 += r.x; x1 += r.y;
                }
                if (OUTBF) {
                    __nv_bfloat162* p = (__nv_bfloat162*)
                        ((bf16*)Cout + (size_t)row * N + col);
                    *p = __floats2bfloat162_rn(x0, x1);
                } else {
                    *(float2*)((float*)Cout + (size_t)row * N + col)
                        = make_float2(x0, x1);
                }
            }
        }
}

// ---------------------------------------------------------------------------
// Tensor-core window attention (Round-7, unchanged)
// ---------------------------------------------------------------------------
__global__ __launch_bounds__(128)
void attn_tc_kernel(const bf16* __restrict__ qkv,
                    const float* __restrict__ rpb,
                    bf16* __restrict__ O, int shifted)
{
    __shared__ bf16 Qs[64 * 40];
    __shared__ bf16 Ks[64 * 40];
    __shared__ bf16 Vs[64 * 40];
    __shared__ float rpbs[2058];
    __shared__ int tok[64];
    __shared__ int regid[64];

    int tid = threadIdx.x;
    int wq = tid >> 5, lane = tid & 31;
    int g = lane >> 2, t = lane & 3;
    int win = blockIdx.x;
    int ws = win >> 8, wh = (win >> 4) & 15, ww = win & 15;

    if (tid < 64) {
        int i = tid >> 4, j = (tid >> 2) & 3, k = tid & 3;
        int cs = ws * 4 + i, ch = wh * 4 + j, cw = ww * 4 + k;
        int sg, hg, wg;
        if (shifted) { sg = (cs + 2) & 31; hg = (ch + 2) & 63; wg = (cw + 2) & 63; }
        else         { sg = cs;            hg = ch;            wg = cw; }
        tok[tid] = (sg * 64 + hg) * 64 + wg;
        int rs = cs < 28 ? 0 : (cs < 30 ? 1 : 2);
        int rh = ch < 60 ? 0 : (ch < 62 ? 1 : 2);
        int rw = cw < 60 ? 0 : (cw < 62 ? 1 : 2);
        regid[tid] = rs * 9 + rh * 3 + rw;
    }
    for (int i = tid; i < 2058; i += 128) rpbs[i] = rpb[i];
    __syncthreads();

    int r0 = wq * 16 + g;
    int r1 = r0 + 8;
    int i0 = r0 >> 4, j0 = (r0 >> 2) & 3, k0 = r0 & 3;
    int i1 = r1 >> 4, j1 = (r1 >> 2) & 3, k1 = r1 & 3;
    int reg0 = regid[r0], reg1 = regid[r1];
    size_t ob0 = (size_t)tok[r0] * C_DIM;
    size_t ob1 = (size_t)tok[r1] * C_DIM;

    int ldrow = (lane & 7) + ((lane >> 3) & 1) * 8;
    int ldcol = (lane >> 4) * 8;
    unsigned qB = (unsigned)__cvta_generic_to_shared(Qs)
                + (unsigned)(((wq * 16 + ldrow) * 40 + ldcol) * 2);
    unsigned kB = (unsigned)__cvta_generic_to_shared(Ks)
                + (unsigned)((ldrow * 40 + ldcol) * 2);
    unsigned vB = (unsigned)__cvta_generic_to_shared(Vs)
                + (unsigned)((ldrow * 40 + ldcol) * 2);

    const float scale = 0.17677669529663687f;

    for (int h = 0; h < 6; h++) {
#pragma unroll
        for (int l = 0; l < 2; l++) {
            int idx = tid + l * 128;
            int row = idx >> 2;
            int c = (idx & 3) * 8;
            const bf16* src = qkv + (size_t)tok[row] * QKV_DIM + h * 32 + c;
            cp_async16(&Qs[row * 40 + c], src);
            cp_async16(&Ks[row * 40 + c], src + 192);
            cp_async16(&Vs[row * 40 + c], src + 384);
        }
        asm volatile("cp.async.commit_group;");
        asm volatile("cp.async.wait_group 0;");
        __syncthreads();

        float s[8][4];
#pragma unroll
        for (int j = 0; j < 8; j++)
#pragma unroll
            for (int e = 0; e < 4; e++) s[j][e] = 0.f;

#pragma unroll
        for (int ks = 0; ks < 2; ks++) {
            unsigned a0, a1, a2, a3;
            ldsm_x4(a0, a1, a2, a3, qB + ks * 32);
#pragma unroll
            for (int nc = 0; nc < 4; nc++) {
                unsigned kr0, kr1, kr2, kr3;
                ldsm_x4(kr0, kr1, kr2, kr3, kB + nc * (16 * 80) + ks * 32);
                mma16816(s[nc * 2],     a0, a1, a2, a3, kr0, kr2);
                mma16816(s[nc * 2 + 1], a0, a1, a2, a3, kr1, kr3);
            }
        }

#pragma unroll
        for (int j = 0; j < 8; j++) {
            int cb = j * 8 + 2 * t;
#pragma unroll
            for (int e = 0; e < 4; e++) {
                int m = cb + (e & 1);
                int im = m >> 4, jm = (m >> 2) & 3, km = m & 3;
                float val;
                if (e < 2) {
                    int idx = (i0 - im + 3) * 49 + (j0 - jm + 3) * 7 + (k0 - km + 3);
                    val = s[j][e] * scale + rpbs[idx * 6 + h];
                    if (shifted && (reg0 != regid[m])) val -= 100.f;
                } else {
                    int idx = (i1 - im + 3) * 49 + (j1 - jm + 3) * 7 + (k1 - km + 3);
                    val = s[j][e] * scale + rpbs[idx * 6 + h];
                    if (shifted && (reg1 != regid[m])) val -= 100.f;
                }
                s[j][e] = val;
            }
        }

        float mx0 = -1e30f, mx1 = -1e30f;
#pragma unroll
        for (int j = 0; j < 8; j++) {
            mx0 = fmaxf(mx0, fmaxf(s[j][0], s[j][1]));
            mx1 = fmaxf(mx1, fmaxf(s[j][2], s[j][3]));
        }
        mx0 = fmaxf(mx0, __shfl_xor_sync(0xffffffffu, mx0, 1));
        mx0 = fmaxf(mx0, __shfl_xor_sync(0xffffffffu, mx0, 2));
        mx1 = fmaxf(mx1, __shfl_xor_sync(0xffffffffu, mx1, 1));
        mx1 = fmaxf(mx1, __shfl_xor_sync(0xffffffffu, mx1, 2));
        float sum0 = 0.f, sum1 = 0.f;
#pragma unroll
        for (int j = 0; j < 8; j++) {
            s[j][0] = __expf(s[j][0] - mx0);
            s[j][1] = __expf(s[j][1] - mx0);
            s[j][2] = __expf(s[j][2] - mx1);
            s[j][3] = __expf(s[j][3] - mx1);
            sum0 += s[j][0] + s[j][1];
            sum1 += s[j][2] + s[j][3];
        }
        sum0 += __shfl_xor_sync(0xffffffffu, sum0, 1);
        sum0 += __shfl_xor_sync(0xffffffffu, sum0, 2);
        sum1 += __shfl_xor_sync(0xffffffffu, sum1, 1);
        sum1 += __shfl_xor_sync(0xffffffffu, sum1, 2);
        float inv0 = 1.0f / sum0, inv1 = 1.0f / sum1;

        unsigned pa[4][4];
#pragma unroll
        for (int kk = 0; kk < 4; kk++) {
            __nv_bfloat162 p0 = __floats2bfloat162_rn(s[2 * kk][0],     s[2 * kk][1]);
            __nv_bfloat162 p1 = __floats2bfloat162_rn(s[2 * kk][2],     s[2 * kk][3]);
            __nv_bfloat162 p2 = __floats2bfloat162_rn(s[2 * kk + 1][0], s[2 * kk + 1][1]);
            __nv_bfloat162 p3 = __floats2bfloat162_rn(s[2 * kk + 1][2], s[2 * kk + 1][3]);
            pa[kk][0] = *(unsigned*)&p0;
            pa[kk][1] = *(unsigned*)&p1;
            pa[kk][2] = *(unsigned*)&p2;
            pa[kk][3] = *(unsigned*)&p3;
        }

        float o[4][4];
#pragma unroll
        for (int j = 0; j < 4; j++)
#pragma unroll
            for (int e = 0; e < 4; e++) o[j][e] = 0.f;

#pragma unroll
        for (int kk = 0; kk < 4; kk++) {
            unsigned v0, v1, v2, v3;
            ldsm_x4_t(v0, v1, v2, v3, vB + kk * (16 * 80));
            mma16816(o[0], pa[kk][0], pa[kk][1], pa[kk][2], pa[kk][3], v0, v1);
            mma16816(o[1], pa[kk][0], pa[kk][1], pa[kk][2], pa[kk][3], v2, v3);
            unsigned w0, w1, w2, w3;
            ldsm_x4_t(w0, w1, w2, w3, vB + kk * (16 * 80) + 32);
            mma16816(o[2], pa[kk][0], pa[kk][1], pa[kk][2], pa[kk][3], w0, w1);
            mma16816(o[3], pa[kk][0], pa[kk][1], pa[kk][2], pa[kk][3], w2, w3);
        }

#pragma unroll
        for (int nt = 0; nt < 4; nt++) {
            int col = h * 32 + nt * 8 + 2 * t;
            *(__nv_bfloat162*)(O + ob0 + col) =
                __floats2bfloat162_rn(o[nt][0] * inv0, o[nt][1] * inv0);
            *(__nv_bfloat162*)(O + ob1 + col) =
                __floats2bfloat162_rn(o[nt][2] * inv1, o[nt][3] * inv1);
        }
        __syncthreads();
    }
}

// ---------------------------------------------------------------------------
static void run_block(const float* Xin, float* Xout,
                      const float* g1, const float* b1,
                      const bf16* qw, const float* qb, const float* rpb,
                      const bf16* pw, const float* pb,
                      const float* g2, const float* b2,
                      const bf16* f1w, const float* f1b,
                      const bf16* f2w, const float* f2b,
                      int shifted,
                      bf16* bufA, bf16* qkv, bf16* obuf, bf16* bufT)
{
    dim3 lnBlk(32, 8);
    int lnGrid = L_TOK / 8;

    ln_kernel<<<lnGrid, lnBlk>>>(Xin, g1, b1, bufA);
    gemm_bf16<false, false, true><<<dim3(QKV_DIM / GBN, L_TOK / GBM), 256, GSMEM>>>(
        bufA, qw, qb, nullptr, qkv, L_TOK, QKV_DIM, C_DIM);
    attn_tc_kernel<<<NWIN, 128>>>(qkv, rpb, obuf, shifted);
    gemm_bf16<false, true, false><<<dim3(C_DIM / GBN, L_TOK / GBM), 256, GSMEM>>>(
        obuf, pw, pb, Xin, Xout, L_TOK, C_DIM, C_DIM);
    ln_kernel<<<lnGrid, lnBlk>>>(Xout, g2, b2, bufA);
    gemm_bf16<true, false, true><<<dim3(FF_DIM / GBN, L_TOK / GBM), 256, GSMEM>>>(
        bufA, f1w, f1b, nullptr, bufT, L_TOK, FF_DIM, C_DIM);
    gemm_bf16<false, true, false><<<dim3(C_DIM / GBN, L_TOK / GBM), 256, GSMEM>>>(
        bufT, f2w, f2b, Xout, Xout, L_TOK, C_DIM, FF_DIM);
}

extern "C" void kernel_launch(void* const* d_in, const int* in_sizes, int n_in,
                              void* d_out, int out_size)
{
    (void)in_sizes; (void)n_in; (void)out_size;
    const float* x = (const float*)d_in[0];
    float* out = (float*)d_out;

    bf16 *bufA, *qkv, *obuf, *bufT, *wbf;
    cudaGetSymbolAddress((void**)&bufA, g_bufA);
    cudaGetSymbolAddress((void**)&qkv,  g_qkv);
    cudaGetSymbolAddress((void**)&obuf, g_obuf);
    cudaGetSymbolAddress((void**)&bufT, g_bufT);
    cudaGetSymbolAddress((void**)&wbf,  g_wbf);

    cudaFuncSetAttribute(gemm_bf16<false, false, true>,
                         cudaFuncAttributeMaxDynamicSharedMemorySize, GSMEM);
    cudaFuncSetAttribute(gemm_bf16<false, true, false>,
                         cudaFuncAttributeMaxDynamicSharedMemorySize, GSMEM);
    cudaFuncSetAttribute(gemm_bf16<true, false, true>,
                         cudaFuncAttributeMaxDynamicSharedMemorySize, GSMEM);

    const int SZ_QW = C_DIM * QKV_DIM;
    const int SZ_PW = C_DIM * C_DIM;
    const int SZ_F1 = C_DIM * FF_DIM;
    const int SZ_F2 = FF_DIM * C_DIM;

    const int widx[8] = { 3, 6, 10, 12, 16, 19, 23, 25 };
    const int wsz [8] = { SZ_QW, SZ_PW, SZ_F1, SZ_F2, SZ_QW, SZ_PW, SZ_F1, SZ_F2 };

    WcvtArgs wa;
    int off = 0;
    bf16* wp[8];
    for (int i = 0; i < 8; i++) {
        wa.src[i] = (const float*)d_in[widx[i]];
        wa.off[i] = off;
        wp[i] = wbf + off;
        off += wsz[i];
    }
    wa.off[8] = off;
    cvt_weights_kernel<<<(off + 255) / 256, 256>>>(wa, wbf);

    run_block(x, out,
              (const float*)d_in[1],  (const float*)d_in[2],
              wp[0],                  (const float*)d_in[4],  (const float*)d_in[5],
              wp[1],                  (const float*)d_in[7],
              (const float*)d_in[8],  (const float*)d_in[9],
              wp[2],                  (const float*)d_in[11],
              wp[3],                  (const float*)d_in[13],
              0, bufA, qkv, obuf, bufT);

    run_block(out, out,
              (const float*)d_in[14], (const float*)d_in[15],
              wp[4],                  (const float*)d_in[17], (const float*)d_in[18],
              wp[5],                  (const float*)d_in[20],
              (const float*)d_in[21], (const float*)d_in[22],
              wp[6],                  (const float*)d_in[24],
              wp[7],                  (const float*)d_in[26],
              1, bufA, qkv, obuf, bufT);
}

// round 13
// speedup vs baseline: 1.2474x; 1.0112x over previous
#include <cuda_runtime.h>
#include <cuda_bf16.h>
#include <math.h>

#define L_TOK 131072
#define C_DIM 192
#define QKV_DIM 576
#define FF_DIM 768
#define NWIN 2048

typedef __nv_bfloat16 bf16;

// scratch (device globals)
__device__ bf16 g_bufA[(size_t)L_TOK * C_DIM];   // LN out (bf16)
__device__ bf16 g_qkv [(size_t)L_TOK * QKV_DIM]; // QKV (bf16)
__device__ bf16 g_obuf[(size_t)L_TOK * C_DIM];   // attn out (bf16)
__device__ bf16 g_bufT[(size_t)L_TOK * FF_DIM];  // MLP hidden (bf16)
__device__ bf16 g_wbf [884736];                  // bf16 weights [K,N]

__device__ __forceinline__ void cp_async16(void* smem, const void* gmem) {
    unsigned saddr = (unsigned)__cvta_generic_to_shared(smem);
    asm volatile("cp.async.cg.shared.global [%0], [%1], 16;\n" :: "r"(saddr), "l"(gmem));
}
__device__ __forceinline__ void ldsm_x4(unsigned& r0, unsigned& r1,
                                        unsigned& r2, unsigned& r3, unsigned addr) {
    asm volatile("ldmatrix.sync.aligned.m8n8.x4.shared.b16 {%0,%1,%2,%3}, [%4];"
                 : "=r"(r0), "=r"(r1), "=r"(r2), "=r"(r3) : "r"(addr));
}
__device__ __forceinline__ void ldsm_x4_t(unsigned& r0, unsigned& r1,
                                          unsigned& r2, unsigned& r3, unsigned addr) {
    asm volatile("ldmatrix.sync.aligned.m8n8.x4.trans.shared.b16 {%0,%1,%2,%3}, [%4];"
                 : "=r"(r0), "=r"(r1), "=r"(r2), "=r"(r3) : "r"(addr));
}
__device__ __forceinline__ void mma16816(float* c, unsigned a0, unsigned a1,
                                         unsigned a2, unsigned a3,
                                         unsigned b0, unsigned b1) {
    asm volatile(
        "mma.sync.aligned.m16n8k16.row.col.f32.bf16.bf16.f32 "
        "{%0,%1,%2,%3},{%4,%5,%6,%7},{%8,%9},{%0,%1,%2,%3};"
        : "+f"(c[0]), "+f"(c[1]), "+f"(c[2]), "+f"(c[3])
        : "r"(a0), "r"(a1), "r"(a2), "r"(a3), "r"(b0), "r"(b1));
}

// ---------------------------------------------------------------------------
// Fused weight conversion
// ---------------------------------------------------------------------------
struct WcvtArgs {
    const float* src[8];
    int off[9];
};

__global__ void cvt_weights_kernel(WcvtArgs a, bf16* __restrict__ out)
{
    int i = blockIdx.x * 256 + threadIdx.x;
    if (i >= a.off[8]) return;
    int s = 0;
#pragma unroll
    for (int j = 1; j < 8; j++) s += (i >= a.off[j]);
    out[i] = __float2bfloat16(a.src[s][i - a.off[s]]);
}

// ---------------------------------------------------------------------------
// LayerNorm, one row per warp; bf16 output
// ---------------------------------------------------------------------------
__global__ void ln_kernel(const float* __restrict__ x,
                          const float* __restrict__ g,
                          const float* __restrict__ b,
                          bf16* __restrict__ out)
{
    int row  = blockIdx.x * 8 + threadIdx.y;
    int lane = threadIdx.x;
    const float* xr = x + (size_t)row * C_DIM;
    float v[6];
    float s = 0.f;
#pragma unroll
    for (int i = 0; i < 6; i++) { v[i] = xr[lane + i * 32]; s += v[i]; }
#pragma unroll
    for (int o = 16; o; o >>= 1) s += __shfl_xor_sync(0xffffffffu, s, o);
    float mu = s * (1.0f / 192.0f);
    float vs = 0.f;
#pragma unroll
    for (int i = 0; i < 6; i++) { float d = v[i] - mu; vs += d * d; }
#pragma unroll
    for (int o = 16; o; o >>= 1) vs += __shfl_xor_sync(0xffffffffu, vs, o);
    float rstd = rsqrtf(vs * (1.0f / 192.0f) + 1e-5f);
    bf16* orow = out + (size_t)row * C_DIM;
#pragma unroll
    for (int i = 0; i < 6; i++) {
        int c = lane + i * 32;
        orow[c] = __float2bfloat16((v[i] - mu) * rstd * g[c] + b[c]);
    }
}

// ---------------------------------------------------------------------------
// bf16 GEMM: BM=128, BN=192, BK=64. 256 thr, 8 warps (4m x 2n),
// warp tile 32x96. 3-stage cp.async ring, ONE __syncthreads per iteration.
// Dynamic smem 132 KB.
// ---------------------------------------------------------------------------
#define GBM 128
#define GBN 192
#define GBK 64
#define ASTRH 72                      // 64 + 8 pad (bf16)
#define BSTRH 200                     // 192 + 8 pad (bf16)
#define ABYTES (GBM * ASTRH * 2)      // 18432
#define BBYTES (GBK * BSTRH * 2)      // 25600
#define STAGEB (ABYTES + BBYTES)      // 44032
#define NSTAGE 3
#define GSMEM  (NSTAGE * STAGEB)      // 132096

template<bool DOGELU, bool RES, bool OUTBF>
__global__ __launch_bounds__(256, 1)
void gemm_bf16(const bf16* __restrict__ A, const bf16* __restrict__ B,
               const float* __restrict__ bias, const float* __restrict__ res,
               void* __restrict__ Cout, int M, int N, int K)
{
    extern __shared__ char smem[];

    int tid = threadIdx.x;
    int bm = blockIdx.y * GBM;
    int bn = blockIdx.x * GBN;
    int wid = tid >> 5, lane = tid & 31;
    int wm = (wid & 3) * 32, wn = (wid >> 2) * 96;
    int g = lane >> 2, t = lane & 3;

    int ldrow = (lane & 7) + ((lane >> 3) & 1) * 8;
    int ldcol = (lane >> 4) * 8;

    unsigned s0 = (unsigned)__cvta_generic_to_shared(smem);
    unsigned aBase = s0 + (unsigned)(((wm + ldrow) * ASTRH + ldcol) * 2);
    unsigned bBase = s0 + (unsigned)(ABYTES + (ldrow * BSTRH + wn + ldcol) * 2);

    float acc[2][12][4];
#pragma unroll
    for (int a = 0; a < 2; a++)
#pragma unroll
        for (int j = 0; j < 12; j++)
#pragma unroll
            for (int c = 0; c < 4; c++) acc[a][j][c] = 0.f;

    auto loadA = [&](int stage, int k0) {
        // 128 rows x 8 chunks(8 bf16) = 1024 -> 4 per thread
#pragma unroll
        for (int l = 0; l < 4; l++) {
            int idx = tid + l * 256;
            int m = idx >> 3;
            int c = (idx & 7) * 8;
            cp_async16(smem + stage * STAGEB + (m * ASTRH + c) * 2,
                       A + (size_t)(bm + m) * K + k0 + c);
        }
    };
    auto loadB = [&](int stage, int k0) {
        // 64 rows x 24 chunks = 1536 -> 6 per thread
#pragma unroll
        for (int l = 0; l < 6; l++) {
            int idx = tid + l * 256;
            int r = idx / 24;
            int c = (idx % 24) * 8;
            cp_async16(smem + stage * STAGEB + ABYTES + (r * BSTRH + c) * 2,
                       B + (size_t)(k0 + r) * N + bn + c);
        }
    };

    int nk = K / GBK;
    loadA(0, 0); loadB(0, 0);
    asm volatile("cp.async.commit_group;");
    if (nk > 1) { loadA(1, GBK); loadB(1, GBK); }
    asm volatile("cp.async.commit_group;");

    for (int kb = 0; kb < nk; kb++) {
        if (kb + 1 < nk) { asm volatile("cp.async.wait_group 1;"); }
        else             { asm volatile("cp.async.wait_group 0;"); }
        __syncthreads();   // all warps past compute(kb-1); stage (kb+2)%3 free

        if (kb + 2 < nk) {
            loadA((kb + 2) % NSTAGE, (kb + 2) * GBK);
            loadB((kb + 2) % NSTAGE, (kb + 2) * GBK);
            asm volatile("cp.async.commit_group;");
        }

        int st = kb % NSTAGE;
        unsigned aS = aBase + st * STAGEB;
        unsigned bS = bBase + st * STAGEB;
#pragma unroll
        for (int ks = 0; ks < 4; ks++) {
            unsigned af[2][4], bfr[6][4];
#pragma unroll
            for (int mt = 0; mt < 2; mt++)
                ldsm_x4(af[mt][0], af[mt][1], af[mt][2], af[mt][3],
                        aS + mt * (16 * ASTRH * 2) + ks * 32);
#pragma unroll
            for (int nt = 0; nt < 6; nt++)
                ldsm_x4_t(bfr[nt][0], bfr[nt][1], bfr[nt][2], bfr[nt][3],
                          bS + ks * (16 * BSTRH * 2) + nt * 32);
#pragma unroll
            for (int mt = 0; mt < 2; mt++)
#pragma unroll
                for (int nt = 0; nt < 6; nt++) {
                    mma16816(acc[mt][nt * 2],     af[mt][0], af[mt][1],
                             af[mt][2], af[mt][3], bfr[nt][0], bfr[nt][1]);
                    mma16816(acc[mt][nt * 2 + 1], af[mt][0], af[mt][1],
                             af[mt][2], af[mt][3], bfr[nt][2], bfr[nt][3]);
                }
        }
    }

#pragma unroll
    for (int mt = 0; mt < 2; mt++)
#pragma unroll
        for (int j = 0; j < 12; j++) {
            int col = bn + wn + j * 8 + 2 * t;
            float2 bv = *(const float2*)(bias + col);
#pragma unroll
            for (int hf = 0; hf < 2; hf++) {
                int row = bm + wm + mt * 16 + g + hf * 8;
                float x0 = acc[mt][j][hf * 2 + 0] + bv.x;
                float x1 = acc[mt][j][hf * 2 + 1] + bv.y;
                if (DOGELU) {
                    x0 = 0.5f * x0 * (1.0f + erff(x0 * 0.70710678118654752f));
                    x1 = 0.5f * x1 * (1.0f + erff(x1 * 0.70710678118654752f));
                }
                if (RES) {
                    float2 r = *(const float2*)(res + (size_t)row * N + col);
                    x0 += r.x; x1 += r.y;
                }
                if (OUTBF) {
                    __nv_bfloat162* p = (__nv_bfloat162*)
                        ((bf16*)Cout + (size_t)row * N + col);
                    *p = __floats2bfloat162_rn(x0, x1);
                } else {
                    *(float2*)((float*)Cout + (size_t)row * N + col)
                        = make_float2(x0, x1);
                }
            }
        }
}

// ---------------------------------------------------------------------------
// Tensor-core window attention (Round-7, unchanged)
// ---------------------------------------------------------------------------
__global__ __launch_bounds__(128)
void attn_tc_kernel(const bf16* __restrict__ qkv,
                    const float* __restrict__ rpb,
                    bf16* __restrict__ O, int shifted)
{
    __shared__ bf16 Qs[64 * 40];
    __shared__ bf16 Ks[64 * 40];
    __shared__ bf16 Vs[64 * 40];
    __shared__ float rpbs[2058];
    __shared__ int tok[64];
    __shared__ int regid[64];

    int tid = threadIdx.x;
    int wq = tid >> 5, lane = tid & 31;
    int g = lane >> 2, t = lane & 3;
    int win = blockIdx.x;
    int ws = win >> 8, wh = (win >> 4) & 15, ww = win & 15;

    if (tid < 64) {
        int i = tid >> 4, j = (tid >> 2) & 3, k = tid & 3;
        int cs = ws * 4 + i, ch = wh * 4 + j, cw = ww * 4 + k;
        int sg, hg, wg;
        if (shifted) { sg = (cs + 2) & 31; hg = (ch + 2) & 63; wg = (cw + 2) & 63; }
        else         { sg = cs;            hg = ch;            wg = cw; }
        tok[tid] = (sg * 64 + hg) * 64 + wg;
        int rs = cs < 28 ? 0 : (cs < 30 ? 1 : 2);
        int rh = ch < 60 ? 0 : (ch < 62 ? 1 : 2);
        int rw = cw < 60 ? 0 : (cw < 62 ? 1 : 2);
        regid[tid] = rs * 9 + rh * 3 + rw;
    }
    for (int i = tid; i < 2058; i += 128) rpbs[i] = rpb[i];
    __syncthreads();

    int r0 = wq * 16 + g;
    int r1 = r0 + 8;
    int i0 = r0 >> 4, j0 = (r0 >> 2) & 3, k0 = r0 & 3;
    int i1 = r1 >> 4, j1 = (r1 >> 2) & 3, k1 = r1 & 3;
    int reg0 = regid[r0], reg1 = regid[r1];
    size_t ob0 = (size_t)tok[r0] * C_DIM;
    size_t ob1 = (size_t)tok[r1] * C_DIM;

    int ldrow = (lane & 7) + ((lane >> 3) & 1) * 8;
    int ldcol = (lane >> 4) * 8;
    unsigned qB = (unsigned)__cvta_generic_to_shared(Qs)
                + (unsigned)(((wq * 16 + ldrow) * 40 + ldcol) * 2);
    unsigned kB = (unsigned)__cvta_generic_to_shared(Ks)
                + (unsigned)((ldrow * 40 + ldcol) * 2);
    unsigned vB = (unsigned)__cvta_generic_to_shared(Vs)
                + (unsigned)((ldrow * 40 + ldcol) * 2);

    const float scale = 0.17677669529663687f;

    for (int h = 0; h < 6; h++) {
#pragma unroll
        for (int l = 0; l < 2; l++) {
            int idx = tid + l * 128;
            int row = idx >> 2;
            int c = (idx & 3) * 8;
            const bf16* src = qkv + (size_t)tok[row] * QKV_DIM + h * 32 + c;
            cp_async16(&Qs[row * 40 + c], src);
            cp_async16(&Ks[row * 40 + c], src + 192);
            cp_async16(&Vs[row * 40 + c], src + 384);
        }
        asm volatile("cp.async.commit_group;");
        asm volatile("cp.async.wait_group 0;");
        __syncthreads();

        float s[8][4];
#pragma unroll
        for (int j = 0; j < 8; j++)
#pragma unroll
            for (int e = 0; e < 4; e++) s[j][e] = 0.f;

#pragma unroll
        for (int ks = 0; ks < 2; ks++) {
            unsigned a0, a1, a2, a3;
            ldsm_x4(a0, a1, a2, a3, qB + ks * 32);
#pragma unroll
            for (int nc = 0; nc < 4; nc++) {
                unsigned kr0, kr1, kr2, kr3;
                ldsm_x4(kr0, kr1, kr2, kr3, kB + nc * (16 * 80) + ks * 32);
                mma16816(s[nc * 2],     a0, a1, a2, a3, kr0, kr2);
                mma16816(s[nc * 2 + 1], a0, a1, a2, a3, kr1, kr3);
            }
        }

#pragma unroll
        for (int j = 0; j < 8; j++) {
            int cb = j * 8 + 2 * t;
#pragma unroll
            for (int e = 0; e < 4; e++) {
                int m = cb + (e & 1);
                int im = m >> 4, jm = (m >> 2) & 3, km = m & 3;
                float val;
                if (e < 2) {
                    int idx = (i0 - im + 3) * 49 + (j0 - jm + 3) * 7 + (k0 - km + 3);
                    val = s[j][e] * scale + rpbs[idx * 6 + h];
                    if (shifted && (reg0 != regid[m])) val -= 100.f;
                } else {
                    int idx = (i1 - im + 3) * 49 + (j1 - jm + 3) * 7 + (k1 - km + 3);
                    val = s[j][e] * scale + rpbs[idx * 6 + h];
                    if (shifted && (reg1 != regid[m])) val -= 100.f;
                }
                s[j][e] = val;
            }
        }

        float mx0 = -1e30f, mx1 = -1e30f;
#pragma unroll
        for (int j = 0; j < 8; j++) {
            mx0 = fmaxf(mx0, fmaxf(s[j][0], s[j][1]));
            mx1 = fmaxf(mx1, fmaxf(s[j][2], s[j][3]));
        }
        mx0 = fmaxf(mx0, __shfl_xor_sync(0xffffffffu, mx0, 1));
        mx0 = fmaxf(mx0, __shfl_xor_sync(0xffffffffu, mx0, 2));
        mx1 = fmaxf(mx1, __shfl_xor_sync(0xffffffffu, mx1, 1));
        mx1 = fmaxf(mx1, __shfl_xor_sync(0xffffffffu, mx1, 2));
        float sum0 = 0.f, sum1 = 0.f;
#pragma unroll
        for (int j = 0; j < 8; j++) {
            s[j][0] = __expf(s[j][0] - mx0);
            s[j][1] = __expf(s[j][1] - mx0);
            s[j][2] = __expf(s[j][2] - mx1);
            s[j][3] = __expf(s[j][3] - mx1);
            sum0 += s[j][0] + s[j][1];
            sum1 += s[j][2] + s[j][3];
        }
        sum0 += __shfl_xor_sync(0xffffffffu, sum0, 1);
        sum0 += __shfl_xor_sync(0xffffffffu, sum0, 2);
        sum1 += __shfl_xor_sync(0xffffffffu, sum1, 1);
        sum1 += __shfl_xor_sync(0xffffffffu, sum1, 2);
        float inv0 = 1.0f / sum0, inv1 = 1.0f / sum1;

        unsigned pa[4][4];
#pragma unroll
        for (int kk = 0; kk < 4; kk++) {
            __nv_bfloat162 p0 = __floats2bfloat162_rn(s[2 * kk][0],     s[2 * kk][1]);
            __nv_bfloat162 p1 = __floats2bfloat162_rn(s[2 * kk][2],     s[2 * kk][3]);
            __nv_bfloat162 p2 = __floats2bfloat162_rn(s[2 * kk + 1][0], s[2 * kk + 1][1]);
            __nv_bfloat162 p3 = __floats2bfloat162_rn(s[2 * kk + 1][2], s[2 * kk + 1][3]);
            pa[kk][0] = *(unsigned*)&p0;
            pa[kk][1] = *(unsigned*)&p1;
            pa[kk][2] = *(unsigned*)&p2;
            pa[kk][3] = *(unsigned*)&p3;
        }

        float o[4][4];
#pragma unroll
        for (int j = 0; j < 4; j++)
#pragma unroll
            for (int e = 0; e < 4; e++) o[j][e] = 0.f;

#pragma unroll
        for (int kk = 0; kk < 4; kk++) {
            unsigned v0, v1, v2, v3;
            ldsm_x4_t(v0, v1, v2, v3, vB + kk * (16 * 80));
            mma16816(o[0], pa[kk][0], pa[kk][1], pa[kk][2], pa[kk][3], v0, v1);
            mma16816(o[1], pa[kk][0], pa[kk][1], pa[kk][2], pa[kk][3], v2, v3);
            unsigned w0, w1, w2, w3;
            ldsm_x4_t(w0, w1, w2, w3, vB + kk * (16 * 80) + 32);
            mma16816(o[2], pa[kk][0], pa[kk][1], pa[kk][2], pa[kk][3], w0, w1);
            mma16816(o[3], pa[kk][0], pa[kk][1], pa[kk][2], pa[kk][3], w2, w3);
        }

#pragma unroll
        for (int nt = 0; nt < 4; nt++) {
            int col = h * 32 + nt * 8 + 2 * t;
            *(__nv_bfloat162*)(O + ob0 + col) =
                __floats2bfloat162_rn(o[nt][0] * inv0, o[nt][1] * inv0);
            *(__nv_bfloat162*)(O + ob1 + col) =
                __floats2bfloat162_rn(o[nt][2] * inv1, o[nt][3] * inv1);
        }
        __syncthreads();
    }
}

// ---------------------------------------------------------------------------
static void run_block(const float* Xin, float* Xout,
                      const float* g1, const float* b1,
                      const bf16* qw, const float* qb, const float* rpb,
                      const bf16* pw, const float* pb,
                      const float* g2, const float* b2,
                      const bf16* f1w, const float* f1b,
                      const bf16* f2w, const float* f2b,
                      int shifted,
                      bf16* bufA, bf16* qkv, bf16* obuf, bf16* bufT)
{
    dim3 lnBlk(32, 8);
    int lnGrid = L_TOK / 8;

    ln_kernel<<<lnGrid, lnBlk>>>(Xin, g1, b1, bufA);
    gemm_bf16<false, false, true><<<dim3(QKV_DIM / GBN, L_TOK / GBM), 256, GSMEM>>>(
        bufA, qw, qb, nullptr, qkv, L_TOK, QKV_DIM, C_DIM);
    attn_tc_kernel<<<NWIN, 128>>>(qkv, rpb, obuf, shifted);
    gemm_bf16<false, true, false><<<dim3(C_DIM / GBN, L_TOK / GBM), 256, GSMEM>>>(
        obuf, pw, pb, Xin, Xout, L_TOK, C_DIM, C_DIM);
    ln_kernel<<<lnGrid, lnBlk>>>(Xout, g2, b2, bufA);
    gemm_bf16<true, false, true><<<dim3(FF_DIM / GBN, L_TOK / GBM), 256, GSMEM>>>(
        bufA, f1w, f1b, nullptr, bufT, L_TOK, FF_DIM, C_DIM);
    gemm_bf16<false, true, false><<<dim3(C_DIM / GBN, L_TOK / GBM), 256, GSMEM>>>(
        bufT, f2w, f2b, Xout, Xout, L_TOK, C_DIM, FF_DIM);
}

extern "C" void kernel_launch(void* const* d_in, const int* in_sizes, int n_in,
                              void* d_out, int out_size)
{
    (void)in_sizes; (void)n_in; (void)out_size;
    const float* x = (const float*)d_in[0];
    float* out = (float*)d_out;

    bf16 *bufA, *qkv, *obuf, *bufT, *wbf;
    cudaGetSymbolAddress((void**)&bufA, g_bufA);
    cudaGetSymbolAddress((void**)&qkv,  g_qkv);
    cudaGetSymbolAddress((void**)&obuf, g_obuf);
    cudaGetSymbolAddress((void**)&bufT, g_bufT);
    cudaGetSymbolAddress((void**)&wbf,  g_wbf);

    cudaFuncSetAttribute(gemm_bf16<false, false, true>,
                         cudaFuncAttributeMaxDynamicSharedMemorySize, GSMEM);
    cudaFuncSetAttribute(gemm_bf16<false, true, false>,
                         cudaFuncAttributeMaxDynamicSharedMemorySize, GSMEM);
    cudaFuncSetAttribute(gemm_bf16<true, false, true>,
                         cudaFuncAttributeMaxDynamicSharedMemorySize, GSMEM);

    const int SZ_QW = C_DIM * QKV_DIM;
    const int SZ_PW = C_DIM * C_DIM;
    const int SZ_F1 = C_DIM * FF_DIM;
    const int SZ_F2 = FF_DIM * C_DIM;

    const int widx[8] = { 3, 6, 10, 12, 16, 19, 23, 25 };
    const int wsz [8] = { SZ_QW, SZ_PW, SZ_F1, SZ_F2, SZ_QW, SZ_PW, SZ_F1, SZ_F2 };

    WcvtArgs wa;
    int off = 0;
    bf16* wp[8];
    for (int i = 0; i < 8; i++) {
        wa.src[i] = (const float*)d_in[widx[i]];
        wa.off[i] = off;
        wp[i] = wbf + off;
        off += wsz[i];
    }
    wa.off[8] = off;
    cvt_weights_kernel<<<(off + 255) / 256, 256>>>(wa, wbf);

    run_block(x, out,
              (const float*)d_in[1],  (const float*)d_in[2],
              wp[0],                  (const float*)d_in[4],  (const float*)d_in[5],
              wp[1],                  (const float*)d_in[7],
              (const float*)d_in[8],  (const float*)d_in[9],
              wp[2],                  (const float*)d_in[11],
              wp[3],                  (const float*)d_in[13],
              0, bufA, qkv, obuf, bufT);

    run_block(out, out,
              (const float*)d_in[14], (const float*)d_in[15],
              wp[4],                  (const float*)d_in[17], (const float*)d_in[18],
              wp[5],                  (const float*)d_in[20],
              (const float*)d_in[21], (const float*)d_in[22],
              wp[6],                  (const float*)d_in[24],
              wp[7],                  (const float*)d_in[26],
              1, bufA, qkv, obuf, bufT);
}